// round 11
// baseline (speedup 1.0000x reference)
#include <cuda_runtime.h>
#include <cuda_fp16.h>
#include <cstdint>
#include <math.h>

#define BATCH 2048
#define UNITS 1024
#define GATES 4096
#define OUTU 256
#define NCOMB 4352            // [Wc | Wd]
#define STEPS 96
#define K0 1280               // step-0 K: [x | h]
#define LDO (STEPS * OUTU)
#define LOSCALE 2048.0f
#define INV_LOSCALE (1.0f / 2048.0f)

// ------------------------------ device scratch ------------------------------
__device__ __align__(256) float g_Wcd[UNITS * NCOMB];   // fp32 combined weights
__device__ __align__(256) float g_bcd[NCOMB];           // combined bias (gate-interleaved + pred)
__device__ __align__(256) float g_b0i[GATES];           // step0 bias (gate-interleaved)
__device__ __align__(256) float g_cf[BATCH * UNITS];    // cell state, FRAGMENT layout
__device__ __align__(256) __half g_h0[BATCH * UNITS];   // h ping-pong (plain fp16)
__device__ __align__(256) __half g_h1[BATCH * UNITS];
__device__ __align__(256) __half g_wthi[(size_t)NCOMB * UNITS];  // W^T hi, interleaved rows
__device__ __align__(256) __half g_wtlo[(size_t)NCOMB * UNITS];  // W^T lo*2048
__device__ __align__(256) __half g_w0hi[(size_t)GATES * K0];     // step0 W^T hi
__device__ __align__(256) __half g_w0lo[(size_t)GATES * K0];     // step0 W^T lo*2048
__device__ __align__(256) __half g_a0[(size_t)BATCH * K0];       // step0 A=[x|h] fp16

__device__ __forceinline__ int icol(int n) {            // gate interleave: unit*4+gate
    return (n < GATES) ? ((n & 1023) * 4 + (n >> 10)) : n;
}

// ------------------------------ PTX helpers ---------------------------------
__device__ __forceinline__ uint32_t smem_u32(const void* p) {
    uint32_t a;
    asm("{ .reg .u64 t; cvta.to.shared.u64 t, %1; cvt.u32.u64 %0, t; }" : "=r"(a) : "l"(p));
    return a;
}
__device__ __forceinline__ uint32_t swz(uint32_t off) { return off ^ ((off >> 3) & 0x70); }
__device__ __forceinline__ void cpa16(uint32_t dst, const void* src) {
    asm volatile("cp.async.cg.shared.global [%0], [%1], 16;" :: "r"(dst), "l"(src) : "memory");
}
#define CP_COMMIT()  asm volatile("cp.async.commit_group;" ::: "memory")
#define CP_WAIT(n)   asm volatile("cp.async.wait_group %0;" :: "n"(n) : "memory")

__device__ __forceinline__ void ldsm4(uint32_t* r, uint32_t addr) {
    asm volatile("ldmatrix.sync.aligned.m8n8.x4.shared.b16 {%0,%1,%2,%3}, [%4];"
        : "=r"(r[0]), "=r"(r[1]), "=r"(r[2]), "=r"(r[3]) : "r"(addr));
}
__device__ __forceinline__ void mma_f32(float* d, const uint32_t* a, uint32_t b0, uint32_t b1) {
    asm volatile("mma.sync.aligned.m16n8k16.row.col.f32.f16.f16.f32 "
        "{%0,%1,%2,%3}, {%4,%5,%6,%7}, {%8,%9}, {%0,%1,%2,%3};"
        : "+f"(d[0]), "+f"(d[1]), "+f"(d[2]), "+f"(d[3])
        : "r"(a[0]), "r"(a[1]), "r"(a[2]), "r"(a[3]), "r"(b0), "r"(b1));
}
__device__ __forceinline__ void mma_f16(uint32_t* d, const uint32_t* a, uint32_t b0, uint32_t b1) {
    asm volatile("mma.sync.aligned.m16n8k16.row.col.f16.f16.f16.f16 "
        "{%0,%1}, {%2,%3,%4,%5}, {%6,%7}, {%0,%1};"
        : "+r"(d[0]), "+r"(d[1])
        : "r"(a[0]), "r"(a[1]), "r"(a[2]), "r"(a[3]), "r"(b0), "r"(b1));
}
// fast sigmoid / tanh via HW exp (error ~2^-17, negligible vs fp16-h noise)
__device__ __forceinline__ float fsig(float x) {
    return 1.0f / (1.0f + __expf(-x));
}
__device__ __forceinline__ float ftanh(float x) {
    float e = __expf(2.0f * x);
    return __fdividef(e - 1.0f, e + 1.0f);
}

// ------------------------------ fused split-GEMM + LSTM ----------------------
// z = A(fp16) @ [Whi + Wlo/2048]^T : main fp32-acc + one fp16-acc correction.
// Tile 128(M)x64(N), 256 thr (4m x 2n warps, 32x32 each), KC=64,
// 3-stage cp.async pipeline (32KB/stage, 96KB/CTA -> 2 CTAs/SM),
// R4-validated skeleton: prefetch BEFORE wait, two syncs per chunk.
// Incremental per-thread global pointers: no per-chunk 64-bit address math.
#define KC 64
#define OFF_AHI 0
#define OFF_BHI 16384
#define OFF_BLO 24576
#define STAGE_BYTES 32768
#define SMEM_TOTAL (3 * STAGE_BYTES)

struct LoadPtrs {
    const __half* a[4];    // A rows (4 per thread)
    const __half* bh[2];   // B hi rows (2 per thread)
    const __half* bl[2];   // B lo rows
    uint32_t soA[4];       // swizzled smem offsets (stage-relative)
    uint32_t soB[2];
};

__device__ __forceinline__ void load_chunk(uint32_t sb, LoadPtrs& P) {
    #pragma unroll
    for (int i = 0; i < 4; ++i) {
        cpa16(sb + OFF_AHI + P.soA[i], P.a[i]);
        P.a[i] += KC;
    }
    #pragma unroll
    for (int i = 0; i < 2; ++i) {
        cpa16(sb + OFF_BHI + P.soB[i], P.bh[i]);
        cpa16(sb + OFF_BLO + P.soB[i], P.bl[i]);
        P.bh[i] += KC;
        P.bl[i] += KC;
    }
    CP_COMMIT();
}

__global__ __launch_bounds__(256, 2)
void bgemm(const __half* __restrict__ a,
           const __half* __restrict__ bhi, const __half* __restrict__ blo,
           int K, const float* __restrict__ bias, int n_tile_off, int t,
           float* __restrict__ outp, __half* __restrict__ hout)
{
    extern __shared__ __align__(1024) char smem[];
    const uint32_t sbase = smem_u32(smem);
    const int tid = threadIdx.x;
    const int lane = tid & 31, w = tid >> 5;
    const int wm = w & 3, wn = w >> 2;             // 4 (m) x 2 (n) warps
    const int r0 = blockIdx.y * 128;
    const int n0 = (blockIdx.x + n_tile_off) * 64;
    const int nch = K / KC;

    // per-thread load pointers (computed once)
    LoadPtrs P;
    {
        int row = tid >> 3, jj = tid & 7;
        #pragma unroll
        for (int i = 0; i < 4; ++i) {
            P.soA[i] = swz((row + i * 32) * 128 + jj * 16);
            P.a[i] = a + (size_t)(r0 + row + i * 32) * K + jj * 8;
        }
        #pragma unroll
        for (int i = 0; i < 2; ++i) {
            P.soB[i] = swz((row + i * 32) * 128 + jj * 16);
            P.bh[i] = bhi + (size_t)(n0 + row + i * 32) * K + jj * 8;
            P.bl[i] = blo + (size_t)(n0 + row + i * 32) * K + jj * 8;
        }
    }

    float dm[2][4][4];
    uint32_t dc[2][4][2];
    #pragma unroll
    for (int mi = 0; mi < 2; ++mi)
        #pragma unroll
        for (int nj = 0; nj < 4; ++nj) {
            #pragma unroll
            for (int q = 0; q < 4; ++q) dm[mi][nj][q] = 0.0f;
            dc[mi][nj][0] = 0u; dc[mi][nj][1] = 0u;
        }

    load_chunk(sbase + 0 * STAGE_BYTES, P);
    load_chunk(sbase + 1 * STAGE_BYTES, P);

    const int lr = lane & 7, sel = lane >> 3;

    for (int kc = 0; kc < nch; ++kc) {
        if (kc + 2 < nch) {
            load_chunk(sbase + ((kc + 2) % 3) * STAGE_BYTES, P);
            CP_WAIT(2);
        } else if (kc + 1 < nch) {
            CP_WAIT(1);
        } else {
            CP_WAIT(0);
        }
        __syncthreads();
        const uint32_t sb = sbase + (kc % 3) * STAGE_BYTES;

        #pragma unroll
        for (int k16 = 0; k16 < 4; ++k16) {
            uint32_t ah[2][4], bh[2][4], bl[2][4];
            #pragma unroll
            for (int mi = 0; mi < 2; ++mi) {
                int row = wm * 32 + mi * 16 + lr + (sel & 1) * 8;
                int kbe = (k16 * 16 + (sel >> 1) * 8) * 2;
                ldsm4(ah[mi], sb + OFF_AHI + swz(row * 128 + kbe));
            }
            #pragma unroll
            for (int njp = 0; njp < 2; ++njp) {
                int nrow = wn * 32 + njp * 16 + lr + (sel >> 1) * 8;
                int kbe = (k16 * 16 + (sel & 1) * 8) * 2;
                uint32_t off = swz(nrow * 128 + kbe);
                ldsm4(bh[njp], sb + OFF_BHI + off);
                ldsm4(bl[njp], sb + OFF_BLO + off);
            }
            #pragma unroll
            for (int mi = 0; mi < 2; ++mi)
                #pragma unroll
                for (int nj = 0; nj < 4; ++nj)
                    mma_f32(dm[mi][nj], ah[mi],
                            bh[nj >> 1][(nj & 1) * 2], bh[nj >> 1][(nj & 1) * 2 + 1]);
            #pragma unroll
            for (int mi = 0; mi < 2; ++mi)
                #pragma unroll
                for (int nj = 0; nj < 4; ++nj)
                    mma_f16(dc[mi][nj], ah[mi],
                            bl[nj >> 1][(nj & 1) * 2], bl[nj >> 1][(nj & 1) * 2 + 1]);
        }
        __syncthreads();
    }

    // ---------------- epilogue ----------------
    const bool isPred = (n0 >= GATES);
    const int qr = lane >> 2, t4 = lane & 3, qc = t4 * 2;
    const bool evenT = ((t4 & 1) == 0);
    // fragment-layout c base (gate tiles only: blockIdx.x < 64)
    const int etid = w * 16 + qr * 2 + (t4 >> 1);            // [0,128)
    const size_t cbase =
        (((size_t)blockIdx.y * 64 + (size_t)blockIdx.x) * 128 + (size_t)etid) * 16;

    #pragma unroll
    for (int mi = 0; mi < 2; ++mi) {
        #pragma unroll
        for (int half = 0; half < 2; ++half) {
            const int r = r0 + wm * 32 + mi * 16 + qr + half * 8;
            float ca[4];
            if (!isPred && evenT)
                *reinterpret_cast<float4*>(ca) =
                    *reinterpret_cast<float4*>(g_cf + cbase + mi * 8 + half * 4);
            #pragma unroll
            for (int nj = 0; nj < 4; ++nj) {
                const int c = wn * 32 + nj * 8 + qc;
                __half2 hc = *reinterpret_cast<__half2*>(&dc[mi][nj][half]);
                float zx = dm[mi][nj][half * 2 + 0]
                         + INV_LOSCALE * __half2float(__low2half(hc)) + bias[n0 + c];
                float zy = dm[mi][nj][half * 2 + 1]
                         + INV_LOSCALE * __half2float(__high2half(hc)) + bias[n0 + c + 1];
                if (isPred) {
                    float2 v = make_float2(zx, zy);
                    *reinterpret_cast<float2*>(
                        outp + (size_t)r * LDO + (size_t)(t - 1) * OUTU + (n0 - GATES) + c) = v;
                } else {
                    // even t4 holds (zi,zf), odd holds (zg,zo) of the same unit
                    float ox = __shfl_xor_sync(0xffffffffu, zx, 1);
                    float oy = __shfl_xor_sync(0xffffffffu, zy, 1);
                    if (evenT) {
                        const int u = ((n0 + c) >> 2);
                        const size_t off = (size_t)r * UNITS + u;
                        float ig = fsig(zx);
                        float fg = fsig(zy);
                        float gg = ftanh(ox);
                        float og = fsig(oy);
                        float cn = fg * ca[nj] + ig * gg;
                        ca[nj] = cn;
                        hout[off] = __float2half_rn(og * ftanh(cn));
                    }
                }
            }
            if (!isPred && evenT)
                *reinterpret_cast<float4*>(g_cf + cbase + mi * 8 + half * 4) =
                    *reinterpret_cast<float4*>(ca);
        }
    }
}

// ------------------------------ merged prep 1 --------------------------------
__global__ void prep1(const float* __restrict__ b, const float* __restrict__ bd,
                      const float* __restrict__ Wk, const float* __restrict__ Wd) {
    int blk = blockIdx.x;
    if (blk < 17) {
        int j = blk * 256 + threadIdx.x;
        if (j < GATES) {
            float s = b[j];
            #pragma unroll 4
            for (int k = 0; k < 256; ++k)
                s += bd[k] * Wk[(size_t)k * GATES + j];
            g_bcd[icol(j)] = s;
            g_b0i[icol(j)] = b[j];
        } else if (j < NCOMB) {
            g_bcd[j] = bd[j - GATES];
        }
    } else {
        int idx = (blk - 17) * 256 + threadIdx.x;
        if (idx < UNITS * OUTU) {
            int r = idx / OUTU, c = idx % OUTU;
            g_Wcd[(size_t)r * NCOMB + GATES + c] = Wd[idx];
        }
    }
}

// ------------------------------ merged prep splits ---------------------------
#define NB_WS 17408
#define NB_W0 20480
#define NB_A0 10240
#define NB_CI 8192
__global__ void prep_splits(const float* __restrict__ Wk, const float* __restrict__ Wr,
                            const float* __restrict__ x0, const float* __restrict__ h0,
                            const float* __restrict__ c0) {
    int blk = blockIdx.x;
    if (blk < NB_WS) {
        int idx = blk * 256 + threadIdx.x;            // over UNITS*NCOMB
        int k = idx / NCOMB, n = idx - k * NCOMB;
        float v = g_Wcd[idx];
        __half hi = __float2half_rn(v);
        size_t o = (size_t)icol(n) * UNITS + k;
        g_wthi[o] = hi;
        g_wtlo[o] = __float2half_rn((v - __half2float(hi)) * LOSCALE);
    } else if (blk < NB_WS + NB_W0) {
        int idx = (blk - NB_WS) * 256 + threadIdx.x;  // over GATES*K0
        int n = idx & (GATES - 1);
        int k = idx >> 12;
        float v = (k < 256) ? Wk[(size_t)k * GATES + n]
                            : Wr[(size_t)(k - 256) * GATES + n];
        __half hi = __float2half_rn(v);
        size_t o = (size_t)icol(n) * K0 + k;
        g_w0hi[o] = hi;
        g_w0lo[o] = __float2half_rn((v - __half2float(hi)) * LOSCALE);
    } else if (blk < NB_WS + NB_W0 + NB_A0) {
        int idx = (blk - NB_WS - NB_W0) * 256 + threadIdx.x;  // over BATCH*K0
        int r = idx / K0, k = idx - r * K0;
        float v = (k < 256) ? x0[(size_t)r * 256 + k] : h0[(size_t)r * UNITS + (k - 256)];
        g_a0[idx] = __float2half_rn(v);
    } else {
        int L = (blk - NB_WS - NB_W0 - NB_A0) * 256 + threadIdx.x;  // over BATCH*UNITS
        int mt = L >> 17;            // 64 nt * 2048 per m-tile
        int rem = L & 131071;
        int nt = rem >> 11;          // 2048 per n-tile
        int rem2 = rem & 2047;
        int etid = rem2 >> 4, pos = rem2 & 15;
        int ww = etid >> 4, q = etid & 15;
        int qr = q >> 1, th = q & 1;
        int wm = ww & 3, wn = ww >> 2;
        int mi = pos >> 3, half = (pos >> 2) & 1, nj = pos & 3;
        int r = mt * 128 + wm * 32 + mi * 16 + qr + half * 8;
        int u = nt * 16 + wn * 8 + nj * 2 + th;
        g_cf[L] = c0[(size_t)r * UNITS + u];
    }
}

// ------------------------------ fp32 prep GEMM -------------------------------
__global__ __launch_bounds__(256)
void sgemm128(const float* __restrict__ A, int lda,
              const float* __restrict__ B, int ldb, int K,
              const float* __restrict__ Cadd,
              float* __restrict__ C, int ldc) {
    __shared__ float As[8][128];
    __shared__ float Bs[8][128];
    const int tid = threadIdx.x;
    const int tx = tid & 15, ty = tid >> 4;
    const int row0 = blockIdx.y * 128, col0 = blockIdx.x * 128;
    float acc[8][8];
    #pragma unroll
    for (int i = 0; i < 8; ++i)
        #pragma unroll
        for (int j = 0; j < 8; ++j) acc[i][j] = 0.0f;
    const int arow = tid >> 1, acol = (tid & 1) << 2;
    const int brow = tid >> 5, bcol = (tid & 31) << 2;
    const float* Arow = A + (size_t)(row0 + arow) * lda + acol;
    const float* Brow = B + (size_t)brow * ldb + col0 + bcol;
    for (int k0 = 0; k0 < K; k0 += 8) {
        float4 av = *reinterpret_cast<const float4*>(Arow + k0);
        float4 bv = *reinterpret_cast<const float4*>(Brow + (size_t)k0 * ldb);
        As[acol + 0][arow] = av.x; As[acol + 1][arow] = av.y;
        As[acol + 2][arow] = av.z; As[acol + 3][arow] = av.w;
        *reinterpret_cast<float4*>(&Bs[brow][bcol]) = bv;
        __syncthreads();
        #pragma unroll
        for (int k = 0; k < 8; ++k) {
            float a[8], bb[8];
            #pragma unroll
            for (int i = 0; i < 8; ++i) a[i] = As[k][ty * 8 + i];
            #pragma unroll
            for (int j = 0; j < 8; ++j) bb[j] = Bs[k][tx * 8 + j];
            #pragma unroll
            for (int i = 0; i < 8; ++i)
                #pragma unroll
                for (int j = 0; j < 8; ++j)
                    acc[i][j] = fmaf(a[i], bb[j], acc[i][j]);
        }
        __syncthreads();
    }
    const int gcol = col0 + tx * 8;
    #pragma unroll
    for (int i = 0; i < 8; ++i) {
        int r = row0 + ty * 8 + i;
        #pragma unroll
        for (int j = 0; j < 8; j += 4) {
            float4 v = make_float4(acc[i][j], acc[i][j+1], acc[i][j+2], acc[i][j+3]);
            if (Cadd) {
                float4 a4 = *reinterpret_cast<const float4*>(Cadd + (size_t)r * ldb + gcol + j);
                v.x += a4.x; v.y += a4.y; v.z += a4.z; v.w += a4.w;
            }
            *reinterpret_cast<float4*>(C + (size_t)r * ldc + gcol + j) = v;
        }
    }
}

// ------------------------------ launch ---------------------------------------
extern "C" void kernel_launch(void* const* d_in, const int* in_sizes, int n_in,
                              void* d_out, int out_size) {
    const float* x0 = (const float*)d_in[0];
    const float* h0 = (const float*)d_in[1];
    const float* c0 = (const float*)d_in[2];
    const float* Wk = (const float*)d_in[3];
    const float* Wr = (const float*)d_in[4];
    const float* b  = (const float*)d_in[5];
    const float* Wd = (const float*)d_in[6];
    const float* bd = (const float*)d_in[7];
    float* out = (float*)d_out;

    cudaFuncSetAttribute(bgemm, cudaFuncAttributeMaxDynamicSharedMemorySize, SMEM_TOTAL);

    float *pWcd, *pBcd, *pB0i;
    __half *pWthi, *pWtlo, *pW0hi, *pW0lo, *pA0, *pH0, *pH1;
    cudaGetSymbolAddress((void**)&pWcd, g_Wcd);
    cudaGetSymbolAddress((void**)&pBcd, g_bcd);
    cudaGetSymbolAddress((void**)&pB0i, g_b0i);
    cudaGetSymbolAddress((void**)&pWthi, g_wthi);
    cudaGetSymbolAddress((void**)&pWtlo, g_wtlo);
    cudaGetSymbolAddress((void**)&pW0hi, g_w0hi);
    cudaGetSymbolAddress((void**)&pW0lo, g_w0lo);
    cudaGetSymbolAddress((void**)&pA0, g_a0);
    cudaGetSymbolAddress((void**)&pH0, g_h0);
    cudaGetSymbolAddress((void**)&pH1, g_h1);

    // prep (3 kernels so ncu's fixed-index capture lands on bgemm)
    prep1<<<17 + 1024, 256>>>(b, bd, Wk, Wd);
    sgemm128<<<dim3(GATES / 128, UNITS / 128), 256>>>(
        Wd, OUTU, Wk, GATES, 256, Wr, pWcd, NCOMB);      // Wc = Wd@Wk + Wr
    prep_splits<<<NB_WS + NB_W0 + NB_A0 + NB_CI, 256>>>(Wk, Wr, x0, h0, c0);

    // h buffers: step t reads hb[t&1], writes hb[(t+1)&1]; step0 writes hb[1]
    __half* hb[2] = {pH0, pH1};

    // step 0: gates only (64 n-tiles), K=1280, fused LSTM -> h1
    bgemm<<<dim3(64, 16), 256, SMEM_TOTAL>>>(
        pA0, pW0hi, pW0lo, K0, pB0i, 0, 0, out, hb[1]);

    // steps 1..95: gates + pred_{t-1} (68 n-tiles), K=1024
    for (int t = 1; t < STEPS; ++t) {
        bgemm<<<dim3(68, 16), 256, SMEM_TOTAL>>>(
            hb[t & 1], pWthi, pWtlo, UNITS, pBcd, 0, t, out, hb[(t + 1) & 1]);
    }

    // final: pred_95 only (4 pred tiles), reads h_96 = hb[0]
    bgemm<<<dim3(4, 16), 256, SMEM_TOTAL>>>(
        hb[0], pWthi, pWtlo, UNITS, pBcd, 64, STEPS, out, hb[1]);
}

// round 12
// speedup vs baseline: 1.5381x; 1.5381x over previous
#include <cuda_runtime.h>
#include <cuda_fp16.h>
#include <cstdint>
#include <math.h>

#define BATCH 2048
#define UNITS 1024
#define GATES 4096
#define OUTU 256
#define NCOMB 4352            // [Wc | Wd]
#define STEPS 96
#define K0 1280               // step-0 K: [x | h]
#define LDO (STEPS * OUTU)
#define LOSCALE 2048.0f
#define INV_LOSCALE (1.0f / 2048.0f)

// ------------------------------ device scratch ------------------------------
__device__ __align__(256) float g_Wcd[UNITS * NCOMB];   // fp32 combined weights
__device__ __align__(256) float g_bcd[NCOMB];           // combined bias (gate-interleaved + pred)
__device__ __align__(256) float g_b0i[GATES];           // step0 bias (gate-interleaved)
__device__ __align__(256) float g_cf[BATCH * UNITS];    // cell state, FRAGMENT layout
__device__ __align__(256) __half g_h0[BATCH * UNITS];   // h ping-pong (plain fp16)
__device__ __align__(256) __half g_h1[BATCH * UNITS];
__device__ __align__(256) __half g_wthi[(size_t)NCOMB * UNITS];  // W^T hi, interleaved rows
__device__ __align__(256) __half g_wtlo[(size_t)NCOMB * UNITS];  // W^T lo*2048
__device__ __align__(256) __half g_w0hi[(size_t)GATES * K0];     // step0 W^T hi
__device__ __align__(256) __half g_w0lo[(size_t)GATES * K0];     // step0 W^T lo*2048
__device__ __align__(256) __half g_a0[(size_t)BATCH * K0];       // step0 A=[x|h] fp16

__device__ __forceinline__ int icol(int n) {            // gate interleave: unit*4+gate
    return (n < GATES) ? ((n & 1023) * 4 + (n >> 10)) : n;
}

// ------------------------------ PTX helpers ---------------------------------
__device__ __forceinline__ uint32_t smem_u32(const void* p) {
    uint32_t a;
    asm("{ .reg .u64 t; cvta.to.shared.u64 t, %1; cvt.u32.u64 %0, t; }" : "=r"(a) : "l"(p));
    return a;
}
__device__ __forceinline__ uint32_t swz(uint32_t off) { return off ^ ((off >> 3) & 0x70); }
__device__ __forceinline__ void cpa16(uint32_t dst, const void* src) {
    asm volatile("cp.async.cg.shared.global [%0], [%1], 16;" :: "r"(dst), "l"(src) : "memory");
}
#define CP_COMMIT()  asm volatile("cp.async.commit_group;" ::: "memory")
#define CP_WAIT(n)   asm volatile("cp.async.wait_group %0;" :: "n"(n) : "memory")

__device__ __forceinline__ void ldsm4(uint32_t* r, uint32_t addr) {
    asm volatile("ldmatrix.sync.aligned.m8n8.x4.shared.b16 {%0,%1,%2,%3}, [%4];"
        : "=r"(r[0]), "=r"(r[1]), "=r"(r[2]), "=r"(r[3]) : "r"(addr));
}
__device__ __forceinline__ void mma_f32(float* d, const uint32_t* a, uint32_t b0, uint32_t b1) {
    asm volatile("mma.sync.aligned.m16n8k16.row.col.f32.f16.f16.f32 "
        "{%0,%1,%2,%3}, {%4,%5,%6,%7}, {%8,%9}, {%0,%1,%2,%3};"
        : "+f"(d[0]), "+f"(d[1]), "+f"(d[2]), "+f"(d[3])
        : "r"(a[0]), "r"(a[1]), "r"(a[2]), "r"(a[3]), "r"(b0), "r"(b1));
}
__device__ __forceinline__ void mma_f16(uint32_t* d, const uint32_t* a, uint32_t b0, uint32_t b1) {
    asm volatile("mma.sync.aligned.m16n8k16.row.col.f16.f16.f16.f16 "
        "{%0,%1}, {%2,%3,%4,%5}, {%6,%7}, {%0,%1};"
        : "+r"(d[0]), "+r"(d[1])
        : "r"(a[0]), "r"(a[1]), "r"(a[2]), "r"(a[3]), "r"(b0), "r"(b1));
}
// fast sigmoid / tanh via HW exp (error ~2^-17, negligible vs fp16-h noise)
__device__ __forceinline__ float fsig(float x) {
    return 1.0f / (1.0f + __expf(-x));
}
__device__ __forceinline__ float ftanh(float x) {
    float e = __expf(2.0f * x);
    return __fdividef(e - 1.0f, e + 1.0f);
}

// ------------------------------ fused split-GEMM + LSTM ----------------------
// z = A(fp16) @ [Whi + Wlo/2048]^T : main fp32-acc + one fp16-acc correction.
// Tile 128(M)x64(N), 256 thr (4m x 2n warps, 32x32 each), KC=64,
// 3-stage cp.async pipeline (32KB/stage, 96KB/CTA -> 2 CTAs/SM),
// R4/R10-validated skeleton: inline address math in load_chunk, prefetch
// BEFORE wait, two syncs per chunk. DO NOT restructure this loop.
#define KC 64
#define OFF_AHI 0
#define OFF_BHI 16384
#define OFF_BLO 24576
#define STAGE_BYTES 32768
#define SMEM_TOTAL (3 * STAGE_BYTES)

__device__ __forceinline__ void load_chunk(
    uint32_t sb, int tid,
    const __half* __restrict__ a,
    const __half* __restrict__ bhi, const __half* __restrict__ blo,
    int r0, int n0, int K, int kc)
{
    const int kcol = kc * KC;
    #pragma unroll
    for (int i = 0; i < 4; ++i) {              // A: 128 rows x 8 chunks of 16B
        int q = tid + i * 256;
        int row = q >> 3, jj = q & 7;
        uint32_t so = swz(row * 128 + jj * 16);
        size_t ga = (size_t)(r0 + row) * K + kcol + jj * 8;
        cpa16(sb + OFF_AHI + so, a + ga);
    }
    #pragma unroll
    for (int i = 0; i < 2; ++i) {              // B: 64 rows x 8 chunks of 16B
        int q = tid + i * 256;
        int row = q >> 3, jj = q & 7;
        uint32_t so = swz(row * 128 + jj * 16);
        size_t gb = (size_t)(n0 + row) * K + kcol + jj * 8;
        cpa16(sb + OFF_BHI + so, bhi + gb);
        cpa16(sb + OFF_BLO + so, blo + gb);
    }
    CP_COMMIT();
}

__global__ __launch_bounds__(256, 2)
void bgemm(const __half* __restrict__ a,
           const __half* __restrict__ bhi, const __half* __restrict__ blo,
           int K, const float* __restrict__ bias, int n_tile_off, int t,
           float* __restrict__ outp, __half* __restrict__ hout)
{
    extern __shared__ __align__(1024) char smem[];
    const uint32_t sbase = smem_u32(smem);
    const int tid = threadIdx.x;
    const int lane = tid & 31, w = tid >> 5;
    const int wm = w & 3, wn = w >> 2;             // 4 (m) x 2 (n) warps
    const int r0 = blockIdx.y * 128;
    const int n0 = (blockIdx.x + n_tile_off) * 64;
    const int nch = K / KC;

    float dm[2][4][4];
    uint32_t dc[2][4][2];
    #pragma unroll
    for (int mi = 0; mi < 2; ++mi)
        #pragma unroll
        for (int nj = 0; nj < 4; ++nj) {
            #pragma unroll
            for (int q = 0; q < 4; ++q) dm[mi][nj][q] = 0.0f;
            dc[mi][nj][0] = 0u; dc[mi][nj][1] = 0u;
        }

    load_chunk(sbase + 0 * STAGE_BYTES, tid, a, bhi, blo, r0, n0, K, 0);
    load_chunk(sbase + 1 * STAGE_BYTES, tid, a, bhi, blo, r0, n0, K, 1);

    const int lr = lane & 7, sel = lane >> 3;

    for (int kc = 0; kc < nch; ++kc) {
        if (kc + 2 < nch) {
            load_chunk(sbase + ((kc + 2) % 3) * STAGE_BYTES, tid,
                       a, bhi, blo, r0, n0, K, kc + 2);
            CP_WAIT(2);
        } else if (kc + 1 < nch) {
            CP_WAIT(1);
        } else {
            CP_WAIT(0);
        }
        __syncthreads();
        const uint32_t sb = sbase + (kc % 3) * STAGE_BYTES;

        #pragma unroll
        for (int k16 = 0; k16 < 4; ++k16) {
            uint32_t ah[2][4], bh[2][4], bl[2][4];
            #pragma unroll
            for (int mi = 0; mi < 2; ++mi) {
                int row = wm * 32 + mi * 16 + lr + (sel & 1) * 8;
                int kbe = (k16 * 16 + (sel >> 1) * 8) * 2;
                ldsm4(ah[mi], sb + OFF_AHI + swz(row * 128 + kbe));
            }
            #pragma unroll
            for (int njp = 0; njp < 2; ++njp) {
                int nrow = wn * 32 + njp * 16 + lr + (sel >> 1) * 8;
                int kbe = (k16 * 16 + (sel & 1) * 8) * 2;
                uint32_t off = swz(nrow * 128 + kbe);
                ldsm4(bh[njp], sb + OFF_BHI + off);
                ldsm4(bl[njp], sb + OFF_BLO + off);
            }
            #pragma unroll
            for (int mi = 0; mi < 2; ++mi)
                #pragma unroll
                for (int nj = 0; nj < 4; ++nj)
                    mma_f32(dm[mi][nj], ah[mi],
                            bh[nj >> 1][(nj & 1) * 2], bh[nj >> 1][(nj & 1) * 2 + 1]);
            #pragma unroll
            for (int mi = 0; mi < 2; ++mi)
                #pragma unroll
                for (int nj = 0; nj < 4; ++nj)
                    mma_f16(dc[mi][nj], ah[mi],
                            bl[nj >> 1][(nj & 1) * 2], bl[nj >> 1][(nj & 1) * 2 + 1]);
        }
        __syncthreads();
    }

    // ---------------- epilogue ----------------
    const bool isPred = (n0 >= GATES);
    const int qr = lane >> 2, t4 = lane & 3, qc = t4 * 2;
    const bool evenT = ((t4 & 1) == 0);
    // fragment-layout c base (gate tiles only: blockIdx.x < 64)
    const int etid = w * 16 + qr * 2 + (t4 >> 1);            // [0,128)
    const size_t cbase =
        (((size_t)blockIdx.y * 64 + (size_t)blockIdx.x) * 128 + (size_t)etid) * 16;

    #pragma unroll
    for (int mi = 0; mi < 2; ++mi) {
        #pragma unroll
        for (int half = 0; half < 2; ++half) {
            const int r = r0 + wm * 32 + mi * 16 + qr + half * 8;
            float ca[4];
            if (!isPred && evenT)
                *reinterpret_cast<float4*>(ca) =
                    *reinterpret_cast<float4*>(g_cf + cbase + mi * 8 + half * 4);
            #pragma unroll
            for (int nj = 0; nj < 4; ++nj) {
                const int c = wn * 32 + nj * 8 + qc;
                __half2 hc = *reinterpret_cast<__half2*>(&dc[mi][nj][half]);
                float zx = dm[mi][nj][half * 2 + 0]
                         + INV_LOSCALE * __half2float(__low2half(hc)) + bias[n0 + c];
                float zy = dm[mi][nj][half * 2 + 1]
                         + INV_LOSCALE * __half2float(__high2half(hc)) + bias[n0 + c + 1];
                if (isPred) {
                    float2 v = make_float2(zx, zy);
                    *reinterpret_cast<float2*>(
                        outp + (size_t)r * LDO + (size_t)(t - 1) * OUTU + (n0 - GATES) + c) = v;
                } else {
                    // even t4 holds (zi,zf), odd holds (zg,zo) of the same unit
                    float ox = __shfl_xor_sync(0xffffffffu, zx, 1);
                    float oy = __shfl_xor_sync(0xffffffffu, zy, 1);
                    if (evenT) {
                        const int u = ((n0 + c) >> 2);
                        const size_t off = (size_t)r * UNITS + u;
                        float ig = fsig(zx);
                        float fg = fsig(zy);
                        float gg = ftanh(ox);
                        float og = fsig(oy);
                        float cn = fg * ca[nj] + ig * gg;
                        ca[nj] = cn;
                        hout[off] = __float2half_rn(og * ftanh(cn));
                    }
                }
            }
            if (!isPred && evenT)
                *reinterpret_cast<float4*>(g_cf + cbase + mi * 8 + half * 4) =
                    *reinterpret_cast<float4*>(ca);
        }
    }
}

// ------------------------------ merged prep 1 --------------------------------
__global__ void prep1(const float* __restrict__ b, const float* __restrict__ bd,
                      const float* __restrict__ Wk, const float* __restrict__ Wd) {
    int blk = blockIdx.x;
    if (blk < 17) {
        int j = blk * 256 + threadIdx.x;
        if (j < GATES) {
            float s = b[j];
            #pragma unroll 4
            for (int k = 0; k < 256; ++k)
                s += bd[k] * Wk[(size_t)k * GATES + j];
            g_bcd[icol(j)] = s;
            g_b0i[icol(j)] = b[j];
        } else if (j < NCOMB) {
            g_bcd[j] = bd[j - GATES];
        }
    } else {
        int idx = (blk - 17) * 256 + threadIdx.x;
        if (idx < UNITS * OUTU) {
            int r = idx / OUTU, c = idx % OUTU;
            g_Wcd[(size_t)r * NCOMB + GATES + c] = Wd[idx];
        }
    }
}

// ------------------------------ merged prep splits ---------------------------
#define NB_WS 17408
#define NB_W0 20480
#define NB_A0 10240
#define NB_CI 8192
__global__ void prep_splits(const float* __restrict__ Wk, const float* __restrict__ Wr,
                            const float* __restrict__ x0, const float* __restrict__ h0,
                            const float* __restrict__ c0) {
    int blk = blockIdx.x;
    if (blk < NB_WS) {
        int idx = blk * 256 + threadIdx.x;            // over UNITS*NCOMB
        int k = idx / NCOMB, n = idx - k * NCOMB;
        float v = g_Wcd[idx];
        __half hi = __float2half_rn(v);
        size_t o = (size_t)icol(n) * UNITS + k;
        g_wthi[o] = hi;
        g_wtlo[o] = __float2half_rn((v - __half2float(hi)) * LOSCALE);
    } else if (blk < NB_WS + NB_W0) {
        int idx = (blk - NB_WS) * 256 + threadIdx.x;  // over GATES*K0
        int n = idx & (GATES - 1);
        int k = idx >> 12;
        float v = (k < 256) ? Wk[(size_t)k * GATES + n]
                            : Wr[(size_t)(k - 256) * GATES + n];
        __half hi = __float2half_rn(v);
        size_t o = (size_t)icol(n) * K0 + k;
        g_w0hi[o] = hi;
        g_w0lo[o] = __float2half_rn((v - __half2float(hi)) * LOSCALE);
    } else if (blk < NB_WS + NB_W0 + NB_A0) {
        int idx = (blk - NB_WS - NB_W0) * 256 + threadIdx.x;  // over BATCH*K0
        int r = idx / K0, k = idx - r * K0;
        float v = (k < 256) ? x0[(size_t)r * 256 + k] : h0[(size_t)r * UNITS + (k - 256)];
        g_a0[idx] = __float2half_rn(v);
    } else {
        int L = (blk - NB_WS - NB_W0 - NB_A0) * 256 + threadIdx.x;  // over BATCH*UNITS
        int mt = L >> 17;            // 64 nt * 2048 per m-tile
        int rem = L & 131071;
        int nt = rem >> 11;          // 2048 per n-tile
        int rem2 = rem & 2047;
        int etid = rem2 >> 4, pos = rem2 & 15;
        int ww = etid >> 4, q = etid & 15;
        int qr = q >> 1, th = q & 1;
        int wm = ww & 3, wn = ww >> 2;
        int mi = pos >> 3, half = (pos >> 2) & 1, nj = pos & 3;
        int r = mt * 128 + wm * 32 + mi * 16 + qr + half * 8;
        int u = nt * 16 + wn * 8 + nj * 2 + th;
        g_cf[L] = c0[(size_t)r * UNITS + u];
    }
}

// ------------------------------ fp32 prep GEMM -------------------------------
__global__ __launch_bounds__(256)
void sgemm128(const float* __restrict__ A, int lda,
              const float* __restrict__ B, int ldb, int K,
              const float* __restrict__ Cadd,
              float* __restrict__ C, int ldc) {
    __shared__ float As[8][128];
    __shared__ float Bs[8][128];
    const int tid = threadIdx.x;
    const int tx = tid & 15, ty = tid >> 4;
    const int row0 = blockIdx.y * 128, col0 = blockIdx.x * 128;
    float acc[8][8];
    #pragma unroll
    for (int i = 0; i < 8; ++i)
        #pragma unroll
        for (int j = 0; j < 8; ++j) acc[i][j] = 0.0f;
    const int arow = tid >> 1, acol = (tid & 1) << 2;
    const int brow = tid >> 5, bcol = (tid & 31) << 2;
    const float* Arow = A + (size_t)(row0 + arow) * lda + acol;
    const float* Brow = B + (size_t)brow * ldb + col0 + bcol;
    for (int k0 = 0; k0 < K; k0 += 8) {
        float4 av = *reinterpret_cast<const float4*>(Arow + k0);
        float4 bv = *reinterpret_cast<const float4*>(Brow + (size_t)k0 * ldb);
        As[acol + 0][arow] = av.x; As[acol + 1][arow] = av.y;
        As[acol + 2][arow] = av.z; As[acol + 3][arow] = av.w;
        *reinterpret_cast<float4*>(&Bs[brow][bcol]) = bv;
        __syncthreads();
        #pragma unroll
        for (int k = 0; k < 8; ++k) {
            float a[8], bb[8];
            #pragma unroll
            for (int i = 0; i < 8; ++i) a[i] = As[k][ty * 8 + i];
            #pragma unroll
            for (int j = 0; j < 8; ++j) bb[j] = Bs[k][tx * 8 + j];
            #pragma unroll
            for (int i = 0; i < 8; ++i)
                #pragma unroll
                for (int j = 0; j < 8; ++j)
                    acc[i][j] = fmaf(a[i], bb[j], acc[i][j]);
        }
        __syncthreads();
    }
    const int gcol = col0 + tx * 8;
    #pragma unroll
    for (int i = 0; i < 8; ++i) {
        int r = row0 + ty * 8 + i;
        #pragma unroll
        for (int j = 0; j < 8; j += 4) {
            float4 v = make_float4(acc[i][j], acc[i][j+1], acc[i][j+2], acc[i][j+3]);
            if (Cadd) {
                float4 a4 = *reinterpret_cast<const float4*>(Cadd + (size_t)r * ldb + gcol + j);
                v.x += a4.x; v.y += a4.y; v.z += a4.z; v.w += a4.w;
            }
            *reinterpret_cast<float4*>(C + (size_t)r * ldc + gcol + j) = v;
        }
    }
}

// ------------------------------ launch ---------------------------------------
extern "C" void kernel_launch(void* const* d_in, const int* in_sizes, int n_in,
                              void* d_out, int out_size) {
    const float* x0 = (const float*)d_in[0];
    const float* h0 = (const float*)d_in[1];
    const float* c0 = (const float*)d_in[2];
    const float* Wk = (const float*)d_in[3];
    const float* Wr = (const float*)d_in[4];
    const float* b  = (const float*)d_in[5];
    const float* Wd = (const float*)d_in[6];
    const float* bd = (const float*)d_in[7];
    float* out = (float*)d_out;

    cudaFuncSetAttribute(bgemm, cudaFuncAttributeMaxDynamicSharedMemorySize, SMEM_TOTAL);

    float *pWcd, *pBcd, *pB0i;
    __half *pWthi, *pWtlo, *pW0hi, *pW0lo, *pA0, *pH0, *pH1;
    cudaGetSymbolAddress((void**)&pWcd, g_Wcd);
    cudaGetSymbolAddress((void**)&pBcd, g_bcd);
    cudaGetSymbolAddress((void**)&pB0i, g_b0i);
    cudaGetSymbolAddress((void**)&pWthi, g_wthi);
    cudaGetSymbolAddress((void**)&pWtlo, g_wtlo);
    cudaGetSymbolAddress((void**)&pW0hi, g_w0hi);
    cudaGetSymbolAddress((void**)&pW0lo, g_w0lo);
    cudaGetSymbolAddress((void**)&pA0, g_a0);
    cudaGetSymbolAddress((void**)&pH0, g_h0);
    cudaGetSymbolAddress((void**)&pH1, g_h1);

    // prep (3 kernels so ncu's fixed-index capture lands on bgemm)
    prep1<<<17 + 1024, 256>>>(b, bd, Wk, Wd);
    sgemm128<<<dim3(GATES / 128, UNITS / 128), 256>>>(
        Wd, OUTU, Wk, GATES, 256, Wr, pWcd, NCOMB);      // Wc = Wd@Wk + Wr
    prep_splits<<<NB_WS + NB_W0 + NB_A0 + NB_CI, 256>>>(Wk, Wr, x0, h0, c0);

    // h buffers: step t reads hb[t&1], writes hb[(t+1)&1]; step0 writes hb[1]
    __half* hb[2] = {pH0, pH1};

    // step 0: gates only (64 n-tiles), K=1280, fused LSTM -> h1
    bgemm<<<dim3(64, 16), 256, SMEM_TOTAL>>>(
        pA0, pW0hi, pW0lo, K0, pB0i, 0, 0, out, hb[1]);

    // steps 1..95: gates + pred_{t-1} (68 n-tiles), K=1024
    for (int t = 1; t < STEPS; ++t) {
        bgemm<<<dim3(68, 16), 256, SMEM_TOTAL>>>(
            hb[t & 1], pWthi, pWtlo, UNITS, pBcd, 0, t, out, hb[(t + 1) & 1]);
    }

    // final: pred_95 only (4 pred tiles), reads h_96 = hb[0]
    bgemm<<<dim3(4, 16), 256, SMEM_TOTAL>>>(
        hb[0], pWthi, pWtlo, UNITS, pBcd, 64, STEPS, out, hb[1]);
}

// round 13
// speedup vs baseline: 1.5526x; 1.0094x over previous
#include <cuda_runtime.h>
#include <cuda_fp16.h>
#include <cstdint>
#include <math.h>

#define BATCH 2048
#define UNITS 1024
#define GATES 4096
#define OUTU 256
#define NCOMB 4352            // [Wc | Wd]
#define STEPS 96
#define K0 1280               // step-0 K: [x | h]
#define LDO (STEPS * OUTU)
#define LOSCALE 2048.0f
#define INV_LOSCALE (1.0f / 2048.0f)

// ------------------------------ device scratch ------------------------------
__device__ __align__(256) float g_Wcd[UNITS * NCOMB];   // fp32 combined weights
__device__ __align__(256) float g_bcd[NCOMB];           // combined bias (gate-interleaved + pred)
__device__ __align__(256) float g_b0i[GATES];           // step0 bias (gate-interleaved)
__device__ __align__(256) float g_cf[BATCH * UNITS];    // cell state, FRAGMENT layout
__device__ __align__(256) __half g_h0[BATCH * UNITS];   // h ping-pong (plain fp16)
__device__ __align__(256) __half g_h1[BATCH * UNITS];
__device__ __align__(256) __half g_wthi[(size_t)NCOMB * UNITS];  // W^T hi, interleaved rows
__device__ __align__(256) __half g_wtlo[(size_t)NCOMB * UNITS];  // W^T lo*2048
__device__ __align__(256) __half g_w0hi[(size_t)GATES * K0];     // step0 W^T hi
__device__ __align__(256) __half g_w0lo[(size_t)GATES * K0];     // step0 W^T lo*2048
__device__ __align__(256) __half g_a0[(size_t)BATCH * K0];       // step0 A=[x|h] fp16

__device__ __forceinline__ int icol(int n) {            // gate interleave: unit*4+gate
    return (n < GATES) ? ((n & 1023) * 4 + (n >> 10)) : n;
}

// ------------------------------ PTX helpers ---------------------------------
__device__ __forceinline__ uint32_t smem_u32(const void* p) {
    uint32_t a;
    asm("{ .reg .u64 t; cvta.to.shared.u64 t, %1; cvt.u32.u64 %0, t; }" : "=r"(a) : "l"(p));
    return a;
}
__device__ __forceinline__ uint32_t swz(uint32_t off) { return off ^ ((off >> 3) & 0x70); }
__device__ __forceinline__ void cpa16(uint32_t dst, const void* src) {
    asm volatile("cp.async.cg.shared.global [%0], [%1], 16;" :: "r"(dst), "l"(src) : "memory");
}
#define CP_COMMIT()  asm volatile("cp.async.commit_group;" ::: "memory")
#define CP_WAIT(n)   asm volatile("cp.async.wait_group %0;" :: "n"(n) : "memory")

// PDL: wait for full completion+visibility of the upstream grid / allow
// dependents to launch early. No-ops when not launched as PDL dependent.
__device__ __forceinline__ void pdl_wait() {
    asm volatile("griddepcontrol.wait;" ::: "memory");
}
__device__ __forceinline__ void pdl_trigger() {
    asm volatile("griddepcontrol.launch_dependents;");
}

__device__ __forceinline__ void ldsm4(uint32_t* r, uint32_t addr) {
    asm volatile("ldmatrix.sync.aligned.m8n8.x4.shared.b16 {%0,%1,%2,%3}, [%4];"
        : "=r"(r[0]), "=r"(r[1]), "=r"(r[2]), "=r"(r[3]) : "r"(addr));
}
__device__ __forceinline__ void mma_f32(float* d, const uint32_t* a, uint32_t b0, uint32_t b1) {
    asm volatile("mma.sync.aligned.m16n8k16.row.col.f32.f16.f16.f32 "
        "{%0,%1,%2,%3}, {%4,%5,%6,%7}, {%8,%9}, {%0,%1,%2,%3};"
        : "+f"(d[0]), "+f"(d[1]), "+f"(d[2]), "+f"(d[3])
        : "r"(a[0]), "r"(a[1]), "r"(a[2]), "r"(a[3]), "r"(b0), "r"(b1));
}
__device__ __forceinline__ void mma_f16(uint32_t* d, const uint32_t* a, uint32_t b0, uint32_t b1) {
    asm volatile("mma.sync.aligned.m16n8k16.row.col.f16.f16.f16.f16 "
        "{%0,%1}, {%2,%3,%4,%5}, {%6,%7}, {%0,%1};"
        : "+r"(d[0]), "+r"(d[1])
        : "r"(a[0]), "r"(a[1]), "r"(a[2]), "r"(a[3]), "r"(b0), "r"(b1));
}
// fast sigmoid / tanh via HW exp (error ~2^-17, negligible vs fp16-h noise)
__device__ __forceinline__ float fsig(float x) {
    return 1.0f / (1.0f + __expf(-x));
}
__device__ __forceinline__ float ftanh(float x) {
    float e = __expf(2.0f * x);
    return __fdividef(e - 1.0f, e + 1.0f);
}

// ------------------------------ fused split-GEMM + LSTM ----------------------
// z = A(fp16) @ [Whi + Wlo/2048]^T : main fp32-acc + one fp16-acc correction.
// Tile 128(M)x64(N), 256 thr (4m x 2n warps, 32x32 each), KC=64,
// 3-stage cp.async pipeline (32KB/stage, 96KB/CTA -> 2 CTAs/SM),
// R4/R10-validated skeleton: inline address math in load_chunk, prefetch
// BEFORE wait, two syncs per chunk. DO NOT restructure the mainloop.
// PDL: prologue preloads constant B chunks before griddepcontrol.wait,
// loads A (= prior step's h) after; trigger fires post-mainloop.
#define KC 64
#define OFF_AHI 0
#define OFF_BHI 16384
#define OFF_BLO 24576
#define STAGE_BYTES 32768
#define SMEM_TOTAL (3 * STAGE_BYTES)

__device__ __forceinline__ void load_chunk(
    uint32_t sb, int tid,
    const __half* __restrict__ a,
    const __half* __restrict__ bhi, const __half* __restrict__ blo,
    int r0, int n0, int K, int kc)
{
    const int kcol = kc * KC;
    #pragma unroll
    for (int i = 0; i < 4; ++i) {              // A: 128 rows x 8 chunks of 16B
        int q = tid + i * 256;
        int row = q >> 3, jj = q & 7;
        uint32_t so = swz(row * 128 + jj * 16);
        size_t ga = (size_t)(r0 + row) * K + kcol + jj * 8;
        cpa16(sb + OFF_AHI + so, a + ga);
    }
    #pragma unroll
    for (int i = 0; i < 2; ++i) {              // B: 64 rows x 8 chunks of 16B
        int q = tid + i * 256;
        int row = q >> 3, jj = q & 7;
        uint32_t so = swz(row * 128 + jj * 16);
        size_t gb = (size_t)(n0 + row) * K + kcol + jj * 8;
        cpa16(sb + OFF_BHI + so, bhi + gb);
        cpa16(sb + OFF_BLO + so, blo + gb);
    }
    CP_COMMIT();
}

// prologue-only split loads (B = weights, constant across steps; A = h)
__device__ __forceinline__ void load_b_chunk(
    uint32_t sb, int tid,
    const __half* __restrict__ bhi, const __half* __restrict__ blo,
    int n0, int K, int kc)
{
    const int kcol = kc * KC;
    #pragma unroll
    for (int i = 0; i < 2; ++i) {
        int q = tid + i * 256;
        int row = q >> 3, jj = q & 7;
        uint32_t so = swz(row * 128 + jj * 16);
        size_t gb = (size_t)(n0 + row) * K + kcol + jj * 8;
        cpa16(sb + OFF_BHI + so, bhi + gb);
        cpa16(sb + OFF_BLO + so, blo + gb);
    }
    CP_COMMIT();
}
__device__ __forceinline__ void load_a_chunk(
    uint32_t sb, int tid, const __half* __restrict__ a,
    int r0, int K, int kc)
{
    const int kcol = kc * KC;
    #pragma unroll
    for (int i = 0; i < 4; ++i) {
        int q = tid + i * 256;
        int row = q >> 3, jj = q & 7;
        uint32_t so = swz(row * 128 + jj * 16);
        size_t ga = (size_t)(r0 + row) * K + kcol + jj * 8;
        cpa16(sb + OFF_AHI + so, a + ga);
    }
    CP_COMMIT();
}

__global__ __launch_bounds__(256, 2)
void bgemm(const __half* __restrict__ a,
           const __half* __restrict__ bhi, const __half* __restrict__ blo,
           int K, const float* __restrict__ bias, int n_tile_off, int t,
           float* __restrict__ outp, __half* __restrict__ hout)
{
    extern __shared__ __align__(1024) char smem[];
    const uint32_t sbase = smem_u32(smem);
    const int tid = threadIdx.x;
    const int lane = tid & 31, w = tid >> 5;
    const int wm = w & 3, wn = w >> 2;             // 4 (m) x 2 (n) warps
    const int r0 = blockIdx.y * 128;
    const int n0 = (blockIdx.x + n_tile_off) * 64;
    const int nch = K / KC;

    float dm[2][4][4];
    uint32_t dc[2][4][2];
    #pragma unroll
    for (int mi = 0; mi < 2; ++mi)
        #pragma unroll
        for (int nj = 0; nj < 4; ++nj) {
            #pragma unroll
            for (int q = 0; q < 4; ++q) dm[mi][nj][q] = 0.0f;
            dc[mi][nj][0] = 0u; dc[mi][nj][1] = 0u;
        }

    // PDL prologue: constant weights first, then wait, then h-dependent A.
    // Commit order: B0, B1, A0, A1 (4 groups) — CP_WAIT counts in the
    // mainloop remain correct (wait_group is by commit order).
    load_b_chunk(sbase + 0 * STAGE_BYTES, tid, bhi, blo, n0, K, 0);
    load_b_chunk(sbase + 1 * STAGE_BYTES, tid, bhi, blo, n0, K, 1);
    pdl_wait();
    load_a_chunk(sbase + 0 * STAGE_BYTES, tid, a, r0, K, 0);
    load_a_chunk(sbase + 1 * STAGE_BYTES, tid, a, r0, K, 1);

    const int lr = lane & 7, sel = lane >> 3;

    for (int kc = 0; kc < nch; ++kc) {
        if (kc + 2 < nch) {
            load_chunk(sbase + ((kc + 2) % 3) * STAGE_BYTES, tid,
                       a, bhi, blo, r0, n0, K, kc + 2);
            CP_WAIT(2);
        } else if (kc + 1 < nch) {
            CP_WAIT(1);
        } else {
            CP_WAIT(0);
        }
        __syncthreads();
        const uint32_t sb = sbase + (kc % 3) * STAGE_BYTES;

        #pragma unroll
        for (int k16 = 0; k16 < 4; ++k16) {
            uint32_t ah[2][4], bh[2][4], bl[2][4];
            #pragma unroll
            for (int mi = 0; mi < 2; ++mi) {
                int row = wm * 32 + mi * 16 + lr + (sel & 1) * 8;
                int kbe = (k16 * 16 + (sel >> 1) * 8) * 2;
                ldsm4(ah[mi], sb + OFF_AHI + swz(row * 128 + kbe));
            }
            #pragma unroll
            for (int njp = 0; njp < 2; ++njp) {
                int nrow = wn * 32 + njp * 16 + lr + (sel >> 1) * 8;
                int kbe = (k16 * 16 + (sel & 1) * 8) * 2;
                uint32_t off = swz(nrow * 128 + kbe);
                ldsm4(bh[njp], sb + OFF_BHI + off);
                ldsm4(bl[njp], sb + OFF_BLO + off);
            }
            #pragma unroll
            for (int mi = 0; mi < 2; ++mi)
                #pragma unroll
                for (int nj = 0; nj < 4; ++nj)
                    mma_f32(dm[mi][nj], ah[mi],
                            bh[nj >> 1][(nj & 1) * 2], bh[nj >> 1][(nj & 1) * 2 + 1]);
            #pragma unroll
            for (int mi = 0; mi < 2; ++mi)
                #pragma unroll
                for (int nj = 0; nj < 4; ++nj)
                    mma_f16(dc[mi][nj], ah[mi],
                            bl[nj >> 1][(nj & 1) * 2], bl[nj >> 1][(nj & 1) * 2 + 1]);
        }
        __syncthreads();
    }

    // allow next step's CTAs to launch and preload their B while we finish
    pdl_trigger();

    // ---------------- epilogue ----------------
    const bool isPred = (n0 >= GATES);
    const int qr = lane >> 2, t4 = lane & 3, qc = t4 * 2;
    const bool evenT = ((t4 & 1) == 0);
    // fragment-layout c base (gate tiles only: blockIdx.x < 64)
    const int etid = w * 16 + qr * 2 + (t4 >> 1);            // [0,128)
    const size_t cbase =
        (((size_t)blockIdx.y * 64 + (size_t)blockIdx.x) * 128 + (size_t)etid) * 16;

    #pragma unroll
    for (int mi = 0; mi < 2; ++mi) {
        #pragma unroll
        for (int half = 0; half < 2; ++half) {
            const int r = r0 + wm * 32 + mi * 16 + qr + half * 8;
            float ca[4];
            if (!isPred && evenT)
                *reinterpret_cast<float4*>(ca) =
                    *reinterpret_cast<float4*>(g_cf + cbase + mi * 8 + half * 4);
            #pragma unroll
            for (int nj = 0; nj < 4; ++nj) {
                const int c = wn * 32 + nj * 8 + qc;
                __half2 hc = *reinterpret_cast<__half2*>(&dc[mi][nj][half]);
                float zx = dm[mi][nj][half * 2 + 0]
                         + INV_LOSCALE * __half2float(__low2half(hc)) + bias[n0 + c];
                float zy = dm[mi][nj][half * 2 + 1]
                         + INV_LOSCALE * __half2float(__high2half(hc)) + bias[n0 + c + 1];
                if (isPred) {
                    float2 v = make_float2(zx, zy);
                    *reinterpret_cast<float2*>(
                        outp + (size_t)r * LDO + (size_t)(t - 1) * OUTU + (n0 - GATES) + c) = v;
                } else {
                    // even t4 holds (zi,zf), odd holds (zg,zo) of the same unit
                    float ox = __shfl_xor_sync(0xffffffffu, zx, 1);
                    float oy = __shfl_xor_sync(0xffffffffu, zy, 1);
                    if (evenT) {
                        const int u = ((n0 + c) >> 2);
                        const size_t off = (size_t)r * UNITS + u;
                        float ig = fsig(zx);
                        float fg = fsig(zy);
                        float gg = ftanh(ox);
                        float og = fsig(oy);
                        float cn = fg * ca[nj] + ig * gg;
                        ca[nj] = cn;
                        hout[off] = __float2half_rn(og * ftanh(cn));
                    }
                }
            }
            if (!isPred && evenT)
                *reinterpret_cast<float4*>(g_cf + cbase + mi * 8 + half * 4) =
                    *reinterpret_cast<float4*>(ca);
        }
    }
}

// ------------------------------ merged prep 1 --------------------------------
__global__ void prep1(const float* __restrict__ b, const float* __restrict__ bd,
                      const float* __restrict__ Wk, const float* __restrict__ Wd) {
    int blk = blockIdx.x;
    if (blk < 17) {
        int j = blk * 256 + threadIdx.x;
        if (j < GATES) {
            float s = b[j];
            #pragma unroll 4
            for (int k = 0; k < 256; ++k)
                s += bd[k] * Wk[(size_t)k * GATES + j];
            g_bcd[icol(j)] = s;
            g_b0i[icol(j)] = b[j];
        } else if (j < NCOMB) {
            g_bcd[j] = bd[j - GATES];
        }
    } else {
        int idx = (blk - 17) * 256 + threadIdx.x;
        if (idx < UNITS * OUTU) {
            int r = idx / OUTU, c = idx % OUTU;
            g_Wcd[(size_t)r * NCOMB + GATES + c] = Wd[idx];
        }
    }
}

// ------------------------------ merged prep splits ---------------------------
#define NB_WS 17408
#define NB_W0 20480
#define NB_A0 10240
#define NB_CI 8192
__global__ void prep_splits(const float* __restrict__ Wk, const float* __restrict__ Wr,
                            const float* __restrict__ x0, const float* __restrict__ h0,
                            const float* __restrict__ c0) {
    int blk = blockIdx.x;
    if (blk < NB_WS) {
        int idx = blk * 256 + threadIdx.x;            // over UNITS*NCOMB
        int k = idx / NCOMB, n = idx - k * NCOMB;
        float v = g_Wcd[idx];
        __half hi = __float2half_rn(v);
        size_t o = (size_t)icol(n) * UNITS + k;
        g_wthi[o] = hi;
        g_wtlo[o] = __float2half_rn((v - __half2float(hi)) * LOSCALE);
    } else if (blk < NB_WS + NB_W0) {
        int idx = (blk - NB_WS) * 256 + threadIdx.x;  // over GATES*K0
        int n = idx & (GATES - 1);
        int k = idx >> 12;
        float v = (k < 256) ? Wk[(size_t)k * GATES + n]
                            : Wr[(size_t)(k - 256) * GATES + n];
        __half hi = __float2half_rn(v);
        size_t o = (size_t)icol(n) * K0 + k;
        g_w0hi[o] = hi;
        g_w0lo[o] = __float2half_rn((v - __half2float(hi)) * LOSCALE);
    } else if (blk < NB_WS + NB_W0 + NB_A0) {
        int idx = (blk - NB_WS - NB_W0) * 256 + threadIdx.x;  // over BATCH*K0
        int r = idx / K0, k = idx - r * K0;
        float v = (k < 256) ? x0[(size_t)r * 256 + k] : h0[(size_t)r * UNITS + (k - 256)];
        g_a0[idx] = __float2half_rn(v);
    } else {
        int L = (blk - NB_WS - NB_W0 - NB_A0) * 256 + threadIdx.x;  // over BATCH*UNITS
        int mt = L >> 17;            // 64 nt * 2048 per m-tile
        int rem = L & 131071;
        int nt = rem >> 11;          // 2048 per n-tile
        int rem2 = rem & 2047;
        int etid = rem2 >> 4, pos = rem2 & 15;
        int ww = etid >> 4, q = etid & 15;
        int qr = q >> 1, th = q & 1;
        int wm = ww & 3, wn = ww >> 2;
        int mi = pos >> 3, half = (pos >> 2) & 1, nj = pos & 3;
        int r = mt * 128 + wm * 32 + mi * 16 + qr + half * 8;
        int u = nt * 16 + wn * 8 + nj * 2 + th;
        g_cf[L] = c0[(size_t)r * UNITS + u];
    }
}

// ------------------------------ fp32 prep GEMM -------------------------------
__global__ __launch_bounds__(256)
void sgemm128(const float* __restrict__ A, int lda,
              const float* __restrict__ B, int ldb, int K,
              const float* __restrict__ Cadd,
              float* __restrict__ C, int ldc) {
    __shared__ float As[8][128];
    __shared__ float Bs[8][128];
    const int tid = threadIdx.x;
    const int tx = tid & 15, ty = tid >> 4;
    const int row0 = blockIdx.y * 128, col0 = blockIdx.x * 128;
    float acc[8][8];
    #pragma unroll
    for (int i = 0; i < 8; ++i)
        #pragma unroll
        for (int j = 0; j < 8; ++j) acc[i][j] = 0.0f;
    const int arow = tid >> 1, acol = (tid & 1) << 2;
    const int brow = tid >> 5, bcol = (tid & 31) << 2;
    const float* Arow = A + (size_t)(row0 + arow) * lda + acol;
    const float* Brow = B + (size_t)brow * ldb + col0 + bcol;
    for (int k0 = 0; k0 < K; k0 += 8) {
        float4 av = *reinterpret_cast<const float4*>(Arow + k0);
        float4 bv = *reinterpret_cast<const float4*>(Brow + (size_t)k0 * ldb);
        As[acol + 0][arow] = av.x; As[acol + 1][arow] = av.y;
        As[acol + 2][arow] = av.z; As[acol + 3][arow] = av.w;
        *reinterpret_cast<float4*>(&Bs[brow][bcol]) = bv;
        __syncthreads();
        #pragma unroll
        for (int k = 0; k < 8; ++k) {
            float a[8], bb[8];
            #pragma unroll
            for (int i = 0; i < 8; ++i) a[i] = As[k][ty * 8 + i];
            #pragma unroll
            for (int j = 0; j < 8; ++j) bb[j] = Bs[k][tx * 8 + j];
            #pragma unroll
            for (int i = 0; i < 8; ++i)
                #pragma unroll
                for (int j = 0; j < 8; ++j)
                    acc[i][j] = fmaf(a[i], bb[j], acc[i][j]);
        }
        __syncthreads();
    }
    const int gcol = col0 + tx * 8;
    #pragma unroll
    for (int i = 0; i < 8; ++i) {
        int r = row0 + ty * 8 + i;
        #pragma unroll
        for (int j = 0; j < 8; j += 4) {
            float4 v = make_float4(acc[i][j], acc[i][j+1], acc[i][j+2], acc[i][j+3]);
            if (Cadd) {
                float4 a4 = *reinterpret_cast<const float4*>(Cadd + (size_t)r * ldb + gcol + j);
                v.x += a4.x; v.y += a4.y; v.z += a4.z; v.w += a4.w;
            }
            *reinterpret_cast<float4*>(C + (size_t)r * ldc + gcol + j) = v;
        }
    }
}

// ------------------------------ launch ---------------------------------------
extern "C" void kernel_launch(void* const* d_in, const int* in_sizes, int n_in,
                              void* d_out, int out_size) {
    const float* x0 = (const float*)d_in[0];
    const float* h0 = (const float*)d_in[1];
    const float* c0 = (const float*)d_in[2];
    const float* Wk = (const float*)d_in[3];
    const float* Wr = (const float*)d_in[4];
    const float* b  = (const float*)d_in[5];
    const float* Wd = (const float*)d_in[6];
    const float* bd = (const float*)d_in[7];
    float* out = (float*)d_out;

    cudaFuncSetAttribute(bgemm, cudaFuncAttributeMaxDynamicSharedMemorySize, SMEM_TOTAL);

    float *pWcd, *pBcd, *pB0i;
    __half *pWthi, *pWtlo, *pW0hi, *pW0lo, *pA0, *pH0, *pH1;
    cudaGetSymbolAddress((void**)&pWcd, g_Wcd);
    cudaGetSymbolAddress((void**)&pBcd, g_bcd);
    cudaGetSymbolAddress((void**)&pB0i, g_b0i);
    cudaGetSymbolAddress((void**)&pWthi, g_wthi);
    cudaGetSymbolAddress((void**)&pWtlo, g_wtlo);
    cudaGetSymbolAddress((void**)&pW0hi, g_w0hi);
    cudaGetSymbolAddress((void**)&pW0lo, g_w0lo);
    cudaGetSymbolAddress((void**)&pA0, g_a0);
    cudaGetSymbolAddress((void**)&pH0, g_h0);
    cudaGetSymbolAddress((void**)&pH1, g_h1);

    // prep (3 kernels so ncu's fixed-index capture lands on bgemm)
    prep1<<<17 + 1024, 256>>>(b, bd, Wk, Wd);
    sgemm128<<<dim3(GATES / 128, UNITS / 128), 256>>>(
        Wd, OUTU, Wk, GATES, 256, Wr, pWcd, NCOMB);      // Wc = Wd@Wk + Wr
    prep_splits<<<NB_WS + NB_W0 + NB_A0 + NB_CI, 256>>>(Wk, Wr, x0, h0, c0);

    // h buffers: step t reads hb[t&1], writes hb[(t+1)&1]; step0 writes hb[1]
    __half* hb[2] = {pH0, pH1};

    // PDL launch config for steps 1..96 (step 0 launches plainly: its B data
    // is produced by prep_splits, so full serialization is required there)
    cudaLaunchAttribute pdlAttr[1];
    pdlAttr[0].id = cudaLaunchAttributeProgrammaticStreamSerialization;
    pdlAttr[0].val.programmaticStreamSerializationAllowed = 1;
    cudaLaunchConfig_t cfg = {};
    cfg.blockDim = dim3(256, 1, 1);
    cfg.dynamicSmemBytes = SMEM_TOTAL;
    cfg.stream = 0;
    cfg.attrs = pdlAttr;
    cfg.numAttrs = 1;

    // step 0: gates only (64 n-tiles), K=1280, fused LSTM -> h1 (plain launch)
    bgemm<<<dim3(64, 16), 256, SMEM_TOTAL>>>(
        pA0, pW0hi, pW0lo, K0, pB0i, 0, 0, out, hb[1]);

    // steps 1..95: gates + pred_{t-1} (68 n-tiles), K=1024, PDL-chained
    for (int t = 1; t < STEPS; ++t) {
        cfg.gridDim = dim3(68, 16, 1);
        cudaLaunchKernelEx(&cfg, bgemm,
            (const __half*)hb[t & 1], (const __half*)pWthi, (const __half*)pWtlo,
            (int)UNITS, (const float*)pBcd, 0, t, out, hb[(t + 1) & 1]);
    }

    // final: pred_95 only (4 pred tiles), reads h_96 = hb[0], PDL-chained
    cfg.gridDim = dim3(4, 16, 1);
    cudaLaunchKernelEx(&cfg, bgemm,
        (const __half*)hb[0], (const __half*)pWthi, (const __half*)pWtlo,
        (int)UNITS, (const float*)pBcd, 64, STEPS, out, hb[1]);
}

// round 14
// speedup vs baseline: 1.6705x; 1.0759x over previous
#include <cuda_runtime.h>
#include <cuda_fp16.h>
#include <cstdint>
#include <math.h>

#define BATCH 2048
#define UNITS 1024
#define GATES 4096
#define OUTU 256
#define NCOMB 4352            // [Wc | Wd]
#define STEPS 96
#define K0 1280               // step-0 K: [x | h]
#define LDO (STEPS * OUTU)
#define LOSCALE 2048.0f
#define INV_LOSCALE (1.0f / 2048.0f)

// persistent-schedule constants
#define T0 1024               // step-0 tiles (64 gate n-tiles x 16 m-rows)
#define TSZ 1088              // tiles per step 1..95 (68 x 16)
#define TTOTAL (T0 + 95 * TSZ + 64)   // + final 64 pred tiles
#define NCTAS 296             // 2 CTAs/SM x 148 SMs (<= resident capacity)

// ------------------------------ device scratch ------------------------------
__device__ __align__(256) float g_Wcd[UNITS * NCOMB];   // fp32 combined weights
__device__ __align__(256) float g_bcd[NCOMB];           // combined bias (gate-interleaved + pred)
__device__ __align__(256) float g_b0i[GATES];           // step0 bias (gate-interleaved)
__device__ __align__(256) float g_cf[BATCH * UNITS];    // cell state, FRAGMENT layout
__device__ __align__(256) __half g_h0[BATCH * UNITS];   // h ping-pong (plain fp16)
__device__ __align__(256) __half g_h1[BATCH * UNITS];
__device__ __align__(256) __half g_wthi[(size_t)NCOMB * UNITS];  // W^T hi, interleaved rows
__device__ __align__(256) __half g_wtlo[(size_t)NCOMB * UNITS];  // W^T lo*2048
__device__ __align__(256) __half g_w0hi[(size_t)GATES * K0];     // step0 W^T hi
__device__ __align__(256) __half g_w0lo[(size_t)GATES * K0];     // step0 W^T lo*2048
__device__ __align__(256) __half g_a0[(size_t)BATCH * K0];       // step0 A=[x|h] fp16
__device__ int g_ticket;                                // global tile ticket
__device__ int g_cnt[STEPS * 16];                       // per-(step, m-row) completion

__device__ __forceinline__ int icol(int n) {            // gate interleave: unit*4+gate
    return (n < GATES) ? ((n & 1023) * 4 + (n >> 10)) : n;
}

// ------------------------------ PTX helpers ---------------------------------
__device__ __forceinline__ uint32_t smem_u32(const void* p) {
    uint32_t a;
    asm("{ .reg .u64 t; cvta.to.shared.u64 t, %1; cvt.u32.u64 %0, t; }" : "=r"(a) : "l"(p));
    return a;
}
__device__ __forceinline__ uint32_t swz(uint32_t off) { return off ^ ((off >> 3) & 0x70); }
__device__ __forceinline__ void cpa16(uint32_t dst, const void* src) {
    asm volatile("cp.async.cg.shared.global [%0], [%1], 16;" :: "r"(dst), "l"(src) : "memory");
}
#define CP_COMMIT()  asm volatile("cp.async.commit_group;" ::: "memory")
#define CP_WAIT(n)   asm volatile("cp.async.wait_group %0;" :: "n"(n) : "memory")

__device__ __forceinline__ void ldsm4(uint32_t* r, uint32_t addr) {
    asm volatile("ldmatrix.sync.aligned.m8n8.x4.shared.b16 {%0,%1,%2,%3}, [%4];"
        : "=r"(r[0]), "=r"(r[1]), "=r"(r[2]), "=r"(r[3]) : "r"(addr));
}
__device__ __forceinline__ void mma_f32(float* d, const uint32_t* a, uint32_t b0, uint32_t b1) {
    asm volatile("mma.sync.aligned.m16n8k16.row.col.f32.f16.f16.f32 "
        "{%0,%1,%2,%3}, {%4,%5,%6,%7}, {%8,%9}, {%0,%1,%2,%3};"
        : "+f"(d[0]), "+f"(d[1]), "+f"(d[2]), "+f"(d[3])
        : "r"(a[0]), "r"(a[1]), "r"(a[2]), "r"(a[3]), "r"(b0), "r"(b1));
}
__device__ __forceinline__ void mma_f16(uint32_t* d, const uint32_t* a, uint32_t b0, uint32_t b1) {
    asm volatile("mma.sync.aligned.m16n8k16.row.col.f16.f16.f16.f16 "
        "{%0,%1}, {%2,%3,%4,%5}, {%6,%7}, {%0,%1};"
        : "+r"(d[0]), "+r"(d[1])
        : "r"(a[0]), "r"(a[1]), "r"(a[2]), "r"(a[3]), "r"(b0), "r"(b1));
}
// fast sigmoid / tanh via HW exp (error ~2^-17, negligible vs fp16-h noise)
__device__ __forceinline__ float fsig(float x) {
    return 1.0f / (1.0f + __expf(-x));
}
__device__ __forceinline__ float ftanh(float x) {
    float e = __expf(2.0f * x);
    return __fdividef(e - 1.0f, e + 1.0f);
}

// ------------------------------ tile pipeline --------------------------------
// z = A(fp16) @ [Whi + Wlo/2048]^T : main fp32-acc + one fp16-acc correction.
// Tile 128(M)x64(N), 256 thr (4m x 2n warps, 32x32 each), KC=64,
// 3-stage cp.async pipeline (32KB/stage, 96KB/CTA -> 2 CTAs/SM).
// R4/R10-validated skeleton: inline address math, prefetch BEFORE wait,
// two syncs per chunk. DO NOT restructure the mainloop.
#define KC 64
#define OFF_AHI 0
#define OFF_BHI 16384
#define OFF_BLO 24576
#define STAGE_BYTES 32768
#define SMEM_TOTAL (3 * STAGE_BYTES)

__device__ __forceinline__ void load_chunk(
    uint32_t sb, int tid,
    const __half* __restrict__ a,
    const __half* __restrict__ bhi, const __half* __restrict__ blo,
    int r0, int n0, int K, int kc)
{
    const int kcol = kc * KC;
    #pragma unroll
    for (int i = 0; i < 4; ++i) {              // A: 128 rows x 8 chunks of 16B
        int q = tid + i * 256;
        int row = q >> 3, jj = q & 7;
        uint32_t so = swz(row * 128 + jj * 16);
        size_t ga = (size_t)(r0 + row) * K + kcol + jj * 8;
        cpa16(sb + OFF_AHI + so, a + ga);
    }
    #pragma unroll
    for (int i = 0; i < 2; ++i) {              // B: 64 rows x 8 chunks of 16B
        int q = tid + i * 256;
        int row = q >> 3, jj = q & 7;
        uint32_t so = swz(row * 128 + jj * 16);
        size_t gb = (size_t)(n0 + row) * K + kcol + jj * 8;
        cpa16(sb + OFF_BHI + so, bhi + gb);
        cpa16(sb + OFF_BLO + so, blo + gb);
    }
    CP_COMMIT();
}

__device__ __forceinline__ void load_b_chunk(
    uint32_t sb, int tid,
    const __half* __restrict__ bhi, const __half* __restrict__ blo,
    int n0, int K, int kc)
{
    const int kcol = kc * KC;
    #pragma unroll
    for (int i = 0; i < 2; ++i) {
        int q = tid + i * 256;
        int row = q >> 3, jj = q & 7;
        uint32_t so = swz(row * 128 + jj * 16);
        size_t gb = (size_t)(n0 + row) * K + kcol + jj * 8;
        cpa16(sb + OFF_BHI + so, bhi + gb);
        cpa16(sb + OFF_BLO + so, blo + gb);
    }
    CP_COMMIT();
}
__device__ __forceinline__ void load_a_chunk(
    uint32_t sb, int tid, const __half* __restrict__ a,
    int r0, int K, int kc)
{
    const int kcol = kc * KC;
    #pragma unroll
    for (int i = 0; i < 4; ++i) {
        int q = tid + i * 256;
        int row = q >> 3, jj = q & 7;
        uint32_t so = swz(row * 128 + jj * 16);
        size_t ga = (size_t)(r0 + row) * K + kcol + jj * 8;
        cpa16(sb + OFF_AHI + so, a + ga);
    }
    CP_COMMIT();
}

// One 128x64 tile: B preload -> dependency spin -> A preload -> mainloop ->
// fused LSTM / pred epilogue. Body identical to the R13 bgemm.
__device__ __forceinline__ void tile_work(
    const __half* __restrict__ a,
    const __half* __restrict__ bhi, const __half* __restrict__ blo,
    int K, const float* __restrict__ bias, int n, int mrow, int t,
    float* __restrict__ outp, __half* __restrict__ hout,
    uint32_t sbase, int tid, volatile int* depcnt, int deptarget)
{
    const int lane = tid & 31, w = tid >> 5;
    const int wm = w & 3, wn = w >> 2;             // 4 (m) x 2 (n) warps
    const int r0 = mrow * 128;
    const int n0 = n * 64;
    const int nch = K / KC;

    float dm[2][4][4];
    uint32_t dc[2][4][2];
    #pragma unroll
    for (int mi = 0; mi < 2; ++mi)
        #pragma unroll
        for (int nj = 0; nj < 4; ++nj) {
            #pragma unroll
            for (int q = 0; q < 4; ++q) dm[mi][nj][q] = 0.0f;
            dc[mi][nj][0] = 0u; dc[mi][nj][1] = 0u;
        }

    // B (constant weights) first; spin on producer row-block; then A.
    load_b_chunk(sbase + 0 * STAGE_BYTES, tid, bhi, blo, n0, K, 0);
    load_b_chunk(sbase + 1 * STAGE_BYTES, tid, bhi, blo, n0, K, 1);
    if (depcnt != nullptr) {
        if (tid == 0) {
            while (*depcnt < deptarget) __nanosleep(128);
            __threadfence();
        }
        __syncthreads();
    }
    load_a_chunk(sbase + 0 * STAGE_BYTES, tid, a, r0, K, 0);
    load_a_chunk(sbase + 1 * STAGE_BYTES, tid, a, r0, K, 1);

    const int lr = lane & 7, sel = lane >> 3;

    for (int kc = 0; kc < nch; ++kc) {
        if (kc + 2 < nch) {
            load_chunk(sbase + ((kc + 2) % 3) * STAGE_BYTES, tid,
                       a, bhi, blo, r0, n0, K, kc + 2);
            CP_WAIT(2);
        } else if (kc + 1 < nch) {
            CP_WAIT(1);
        } else {
            CP_WAIT(0);
        }
        __syncthreads();
        const uint32_t sb = sbase + (kc % 3) * STAGE_BYTES;

        #pragma unroll
        for (int k16 = 0; k16 < 4; ++k16) {
            uint32_t ah[2][4], bh[2][4], bl[2][4];
            #pragma unroll
            for (int mi = 0; mi < 2; ++mi) {
                int row = wm * 32 + mi * 16 + lr + (sel & 1) * 8;
                int kbe = (k16 * 16 + (sel >> 1) * 8) * 2;
                ldsm4(ah[mi], sb + OFF_AHI + swz(row * 128 + kbe));
            }
            #pragma unroll
            for (int njp = 0; njp < 2; ++njp) {
                int nrow = wn * 32 + njp * 16 + lr + (sel >> 1) * 8;
                int kbe = (k16 * 16 + (sel & 1) * 8) * 2;
                uint32_t off = swz(nrow * 128 + kbe);
                ldsm4(bh[njp], sb + OFF_BHI + off);
                ldsm4(bl[njp], sb + OFF_BLO + off);
            }
            #pragma unroll
            for (int mi = 0; mi < 2; ++mi)
                #pragma unroll
                for (int nj = 0; nj < 4; ++nj)
                    mma_f32(dm[mi][nj], ah[mi],
                            bh[nj >> 1][(nj & 1) * 2], bh[nj >> 1][(nj & 1) * 2 + 1]);
            #pragma unroll
            for (int mi = 0; mi < 2; ++mi)
                #pragma unroll
                for (int nj = 0; nj < 4; ++nj)
                    mma_f16(dc[mi][nj], ah[mi],
                            bl[nj >> 1][(nj & 1) * 2], bl[nj >> 1][(nj & 1) * 2 + 1]);
        }
        __syncthreads();
    }

    // ---------------- epilogue ----------------
    const bool isPred = (n0 >= GATES);
    const int qr = lane >> 2, t4 = lane & 3, qc = t4 * 2;
    const bool evenT = ((t4 & 1) == 0);
    const int etid = w * 16 + qr * 2 + (t4 >> 1);            // [0,128)
    const size_t cbase =
        (((size_t)mrow * 64 + (size_t)n) * 128 + (size_t)etid) * 16;

    #pragma unroll
    for (int mi = 0; mi < 2; ++mi) {
        #pragma unroll
        for (int half = 0; half < 2; ++half) {
            const int r = r0 + wm * 32 + mi * 16 + qr + half * 8;
            float4 ca4;
            float* ca = &ca4.x;
            if (!isPred && evenT)
                ca4 = __ldcg(reinterpret_cast<const float4*>(
                    g_cf + cbase + mi * 8 + half * 4));     // L2 (L1 not coherent in-kernel)
            #pragma unroll
            for (int nj = 0; nj < 4; ++nj) {
                const int c = wn * 32 + nj * 8 + qc;
                __half2 hc = *reinterpret_cast<__half2*>(&dc[mi][nj][half]);
                float zx = dm[mi][nj][half * 2 + 0]
                         + INV_LOSCALE * __half2float(__low2half(hc)) + bias[n0 + c];
                float zy = dm[mi][nj][half * 2 + 1]
                         + INV_LOSCALE * __half2float(__high2half(hc)) + bias[n0 + c + 1];
                if (isPred) {
                    float2 v = make_float2(zx, zy);
                    *reinterpret_cast<float2*>(
                        outp + (size_t)r * LDO + (size_t)(t - 1) * OUTU + (n0 - GATES) + c) = v;
                } else {
                    // even t4 holds (zi,zf), odd holds (zg,zo) of the same unit
                    float ox = __shfl_xor_sync(0xffffffffu, zx, 1);
                    float oy = __shfl_xor_sync(0xffffffffu, zy, 1);
                    if (evenT) {
                        const int u = ((n0 + c) >> 2);
                        const size_t off = (size_t)r * UNITS + u;
                        float ig = fsig(zx);
                        float fg = fsig(zy);
                        float gg = ftanh(ox);
                        float og = fsig(oy);
                        float cn = fg * ca[nj] + ig * gg;
                        ca[nj] = cn;
                        hout[off] = __float2half_rn(og * ftanh(cn));
                    }
                }
            }
            if (!isPred && evenT)
                __stcg(reinterpret_cast<float4*>(g_cf + cbase + mi * 8 + half * 4), ca4);
        }
    }
}

// ------------------------------ persistent kernel ----------------------------
__global__ __launch_bounds__(256, 2)
void pbgemm(float* __restrict__ outp)
{
    extern __shared__ __align__(1024) char smem[];
    const uint32_t sbase = smem_u32(smem);
    const int tid = threadIdx.x;
    __shared__ int s_id;

    for (;;) {
        if (tid == 0) s_id = atomicAdd(&g_ticket, 1);
        __syncthreads();
        const int id = s_id;
        if (id >= TTOTAL) break;

        const __half *A, *BH, *BL;
        const float* bias;
        __half* hout;
        int K, n, mrow, t;
        volatile int* dep = nullptr;
        int tgt = 0;

        if (id < T0) {                                   // step 0: gates only
            t = 0; mrow = id >> 6; n = id & 63;
            A = g_a0; BH = g_w0hi; BL = g_w0lo; K = K0;
            bias = g_b0i; hout = g_h1;
        } else if (id < T0 + 95 * TSZ) {                 // steps 1..95
            int q = id - T0;
            t = 1 + q / TSZ;
            int rem = q - (t - 1) * TSZ;
            mrow = rem / 68; n = rem - mrow * 68;
            A = (t & 1) ? g_h1 : g_h0;                   // hb[t&1]
            hout = ((t + 1) & 1) ? g_h1 : g_h0;          // hb[(t+1)&1]
            BH = g_wthi; BL = g_wtlo; K = UNITS; bias = g_bcd;
            dep = (volatile int*)&g_cnt[(t - 1) * 16 + mrow];
            tgt = (t == 1) ? 64 : 68;
        } else {                                         // final pred_95 tiles
            int rem = id - (T0 + 95 * TSZ);
            t = STEPS; mrow = rem >> 2; n = 64 + (rem & 3);
            A = g_h0;                                    // h_96 = hb[0]
            hout = g_h1;                                 // unused (pred only)
            BH = g_wthi; BL = g_wtlo; K = UNITS; bias = g_bcd;
            dep = (volatile int*)&g_cnt[95 * 16 + mrow];
            tgt = 68;
        }

        tile_work(A, BH, BL, K, bias, n, mrow, t, outp, hout,
                  sbase, tid, dep, tgt);

        __threadfence();
        __syncthreads();
        if (tid == 0 && t < STEPS)
            atomicAdd(&g_cnt[t * 16 + mrow], 1);
    }
}

// ------------------------------ merged prep 1 --------------------------------
__global__ void prep1(const float* __restrict__ b, const float* __restrict__ bd,
                      const float* __restrict__ Wk, const float* __restrict__ Wd) {
    int blk = blockIdx.x;
    if (blk < 17) {
        int j = blk * 256 + threadIdx.x;
        if (j < GATES) {
            float s = b[j];
            #pragma unroll 4
            for (int k = 0; k < 256; ++k)
                s += bd[k] * Wk[(size_t)k * GATES + j];
            g_bcd[icol(j)] = s;
            g_b0i[icol(j)] = b[j];
        } else if (j < NCOMB) {
            g_bcd[j] = bd[j - GATES];
        }
    } else {
        int idx = (blk - 17) * 256 + threadIdx.x;
        if (idx < UNITS * OUTU) {
            int r = idx / OUTU, c = idx % OUTU;
            g_Wcd[(size_t)r * NCOMB + GATES + c] = Wd[idx];
        }
    }
}

// ------------------------------ merged prep splits ---------------------------
#define NB_WS 17408
#define NB_W0 20480
#define NB_A0 10240
#define NB_CI 8192
__global__ void prep_splits(const float* __restrict__ Wk, const float* __restrict__ Wr,
                            const float* __restrict__ x0, const float* __restrict__ h0,
                            const float* __restrict__ c0) {
    int blk = blockIdx.x;
    if (blk < NB_WS) {
        int idx = blk * 256 + threadIdx.x;            // over UNITS*NCOMB
        int k = idx / NCOMB, n = idx - k * NCOMB;
        float v = g_Wcd[idx];
        __half hi = __float2half_rn(v);
        size_t o = (size_t)icol(n) * UNITS + k;
        g_wthi[o] = hi;
        g_wtlo[o] = __float2half_rn((v - __half2float(hi)) * LOSCALE);
    } else if (blk < NB_WS + NB_W0) {
        int idx = (blk - NB_WS) * 256 + threadIdx.x;  // over GATES*K0
        int n = idx & (GATES - 1);
        int k = idx >> 12;
        float v = (k < 256) ? Wk[(size_t)k * GATES + n]
                            : Wr[(size_t)(k - 256) * GATES + n];
        __half hi = __float2half_rn(v);
        size_t o = (size_t)icol(n) * K0 + k;
        g_w0hi[o] = hi;
        g_w0lo[o] = __float2half_rn((v - __half2float(hi)) * LOSCALE);
    } else if (blk < NB_WS + NB_W0 + NB_A0) {
        int idx = (blk - NB_WS - NB_W0) * 256 + threadIdx.x;  // over BATCH*K0
        int r = idx / K0, k = idx - r * K0;
        float v = (k < 256) ? x0[(size_t)r * 256 + k] : h0[(size_t)r * UNITS + (k - 256)];
        g_a0[idx] = __float2half_rn(v);
    } else {
        int L = (blk - NB_WS - NB_W0 - NB_A0) * 256 + threadIdx.x;  // over BATCH*UNITS
        int mt = L >> 17;            // 64 nt * 2048 per m-tile
        int rem = L & 131071;
        int nt = rem >> 11;          // 2048 per n-tile
        int rem2 = rem & 2047;
        int etid = rem2 >> 4, pos = rem2 & 15;
        int ww = etid >> 4, q = etid & 15;
        int qr = q >> 1, th = q & 1;
        int wm = ww & 3, wn = ww >> 2;
        int mi = pos >> 3, half = (pos >> 2) & 1, nj = pos & 3;
        int r = mt * 128 + wm * 32 + mi * 16 + qr + half * 8;
        int u = nt * 16 + wn * 8 + nj * 2 + th;
        g_cf[L] = c0[(size_t)r * UNITS + u];
    }
}

// ------------------------------ fp32 prep GEMM -------------------------------
__global__ __launch_bounds__(256)
void sgemm128(const float* __restrict__ A, int lda,
              const float* __restrict__ B, int ldb, int K,
              const float* __restrict__ Cadd,
              float* __restrict__ C, int ldc) {
    __shared__ float As[8][128];
    __shared__ float Bs[8][128];
    const int tid = threadIdx.x;
    const int tx = tid & 15, ty = tid >> 4;
    const int row0 = blockIdx.y * 128, col0 = blockIdx.x * 128;
    float acc[8][8];
    #pragma unroll
    for (int i = 0; i < 8; ++i)
        #pragma unroll
        for (int j = 0; j < 8; ++j) acc[i][j] = 0.0f;
    const int arow = tid >> 1, acol = (tid & 1) << 2;
    const int brow = tid >> 5, bcol = (tid & 31) << 2;
    const float* Arow = A + (size_t)(row0 + arow) * lda + acol;
    const float* Brow = B + (size_t)brow * ldb + col0 + bcol;
    for (int k0 = 0; k0 < K; k0 += 8) {
        float4 av = *reinterpret_cast<const float4*>(Arow + k0);
        float4 bv = *reinterpret_cast<const float4*>(Brow + (size_t)k0 * ldb);
        As[acol + 0][arow] = av.x; As[acol + 1][arow] = av.y;
        As[acol + 2][arow] = av.z; As[acol + 3][arow] = av.w;
        *reinterpret_cast<float4*>(&Bs[brow][bcol]) = bv;
        __syncthreads();
        #pragma unroll
        for (int k = 0; k < 8; ++k) {
            float a[8], bb[8];
            #pragma unroll
            for (int i = 0; i < 8; ++i) a[i] = As[k][ty * 8 + i];
            #pragma unroll
            for (int j = 0; j < 8; ++j) bb[j] = Bs[k][tx * 8 + j];
            #pragma unroll
            for (int i = 0; i < 8; ++i)
                #pragma unroll
                for (int j = 0; j < 8; ++j)
                    acc[i][j] = fmaf(a[i], bb[j], acc[i][j]);
        }
        __syncthreads();
    }
    const int gcol = col0 + tx * 8;
    #pragma unroll
    for (int i = 0; i < 8; ++i) {
        int r = row0 + ty * 8 + i;
        #pragma unroll
        for (int j = 0; j < 8; j += 4) {
            float4 v = make_float4(acc[i][j], acc[i][j+1], acc[i][j+2], acc[i][j+3]);
            if (Cadd) {
                float4 a4 = *reinterpret_cast<const float4*>(Cadd + (size_t)r * ldb + gcol + j);
                v.x += a4.x; v.y += a4.y; v.z += a4.z; v.w += a4.w;
            }
            *reinterpret_cast<float4*>(C + (size_t)r * ldc + gcol + j) = v;
        }
    }
}

// ------------------------------ launch ---------------------------------------
extern "C" void kernel_launch(void* const* d_in, const int* in_sizes, int n_in,
                              void* d_out, int out_size) {
    const float* x0 = (const float*)d_in[0];
    const float* h0 = (const float*)d_in[1];
    const float* c0 = (const float*)d_in[2];
    const float* Wk = (const float*)d_in[3];
    const float* Wr = (const float*)d_in[4];
    const float* b  = (const float*)d_in[5];
    const float* Wd = (const float*)d_in[6];
    const float* bd = (const float*)d_in[7];
    float* out = (float*)d_out;

    cudaFuncSetAttribute(pbgemm, cudaFuncAttributeMaxDynamicSharedMemorySize, SMEM_TOTAL);

    float* pWcd;
    int *pTicket, *pCnt;
    cudaGetSymbolAddress((void**)&pWcd, g_Wcd);
    cudaGetSymbolAddress((void**)&pTicket, g_ticket);
    cudaGetSymbolAddress((void**)&pCnt, g_cnt);

    // reset persistent-schedule state (graph-replay-safe, deterministic)
    cudaMemsetAsync(pTicket, 0, sizeof(int), 0);
    cudaMemsetAsync(pCnt, 0, STEPS * 16 * sizeof(int), 0);

    // prep
    prep1<<<17 + 1024, 256>>>(b, bd, Wk, Wd);
    sgemm128<<<dim3(GATES / 128, UNITS / 128), 256>>>(
        Wd, OUTU, Wk, GATES, 256, Wr, pWcd, NCOMB);      // Wc = Wd@Wk + Wr
    prep_splits<<<NB_WS + NB_W0 + NB_A0 + NB_CI, 256>>>(Wk, Wr, x0, h0, c0);

    // all 97 steps in ONE persistent launch (ticket + per-(step,mrow) deps)
    pbgemm<<<NCTAS, 256, SMEM_TOTAL>>>(out);
}

// round 15
// speedup vs baseline: 1.6962x; 1.0154x over previous
#include <cuda_runtime.h>
#include <cuda_fp16.h>
#include <cstdint>
#include <math.h>

#define BATCH 2048
#define UNITS 1024
#define GATES 4096
#define OUTU 256
#define NCOMB 4352            // [Wc | Wd]
#define STEPS 96
#define K0 1280               // step-0 K: [x | h]
#define LDO (STEPS * OUTU)
#define LOSCALE 2048.0f
#define INV_LOSCALE (1.0f / 2048.0f)

// persistent-schedule constants
#define T0 1024               // step-0 tiles (64 gate n-tiles x 16 m-rows)
#define TSZ 1088              // tiles per step 1..95 (1024 gates + 64 preds)
#define TTOTAL (T0 + 95 * TSZ + 64)   // + final 64 pred tiles
#define NCTAS 296             // 2 CTAs/SM x 148 SMs

// ------------------------------ device scratch ------------------------------
__device__ __align__(256) float g_Wcd[UNITS * NCOMB];   // fp32 combined weights
__device__ __align__(256) float g_bcd[NCOMB];           // combined bias (gate-interleaved + pred)
__device__ __align__(256) float g_b0i[GATES];           // step0 bias (gate-interleaved)
__device__ __align__(256) float g_cf[BATCH * UNITS];    // cell state, FRAGMENT layout
__device__ __align__(256) __half g_h0[BATCH * UNITS];   // h ping-pong (plain fp16)
__device__ __align__(256) __half g_h1[BATCH * UNITS];
__device__ __align__(256) __half g_wthi[(size_t)NCOMB * UNITS];  // W^T hi, interleaved rows
__device__ __align__(256) __half g_wtlo[(size_t)NCOMB * UNITS];  // W^T lo*2048
__device__ __align__(256) __half g_w0hi[(size_t)GATES * K0];     // step0 W^T hi
__device__ __align__(256) __half g_w0lo[(size_t)GATES * K0];     // step0 W^T lo*2048
__device__ __align__(256) __half g_a0[(size_t)BATCH * K0];       // step0 A=[x|h] fp16
__device__ int g_ticket;                                // global tile ticket
__device__ int g_cnt[STEPS * 16];                       // per-(step, m-row) GATE completions

__device__ __forceinline__ int icol(int n) {            // gate interleave: unit*4+gate
    return (n < GATES) ? ((n & 1023) * 4 + (n >> 10)) : n;
}

// ------------------------------ PTX helpers ---------------------------------
__device__ __forceinline__ uint32_t smem_u32(const void* p) {
    uint32_t a;
    asm("{ .reg .u64 t; cvta.to.shared.u64 t, %1; cvt.u32.u64 %0, t; }" : "=r"(a) : "l"(p));
    return a;
}
__device__ __forceinline__ uint32_t swz(uint32_t off) { return off ^ ((off >> 3) & 0x70); }
__device__ __forceinline__ void cpa16(uint32_t dst, const void* src) {
    asm volatile("cp.async.cg.shared.global [%0], [%1], 16;" :: "r"(dst), "l"(src) : "memory");
}
#define CP_COMMIT()  asm volatile("cp.async.commit_group;" ::: "memory")
#define CP_WAIT(n)   asm volatile("cp.async.wait_group %0;" :: "n"(n) : "memory")

__device__ __forceinline__ void ldsm4(uint32_t* r, uint32_t addr) {
    asm volatile("ldmatrix.sync.aligned.m8n8.x4.shared.b16 {%0,%1,%2,%3}, [%4];"
        : "=r"(r[0]), "=r"(r[1]), "=r"(r[2]), "=r"(r[3]) : "r"(addr));
}
__device__ __forceinline__ void mma_f32(float* d, const uint32_t* a, uint32_t b0, uint32_t b1) {
    asm volatile("mma.sync.aligned.m16n8k16.row.col.f32.f16.f16.f32 "
        "{%0,%1,%2,%3}, {%4,%5,%6,%7}, {%8,%9}, {%0,%1,%2,%3};"
        : "+f"(d[0]), "+f"(d[1]), "+f"(d[2]), "+f"(d[3])
        : "r"(a[0]), "r"(a[1]), "r"(a[2]), "r"(a[3]), "r"(b0), "r"(b1));
}
__device__ __forceinline__ void mma_f16(uint32_t* d, const uint32_t* a, uint32_t b0, uint32_t b1) {
    asm volatile("mma.sync.aligned.m16n8k16.row.col.f16.f16.f16.f16 "
        "{%0,%1}, {%2,%3,%4,%5}, {%6,%7}, {%0,%1};"
        : "+r"(d[0]), "+r"(d[1])
        : "r"(a[0]), "r"(a[1]), "r"(a[2]), "r"(a[3]), "r"(b0), "r"(b1));
}
// fast sigmoid / tanh via HW exp (error ~2^-17, negligible vs fp16-h noise)
__device__ __forceinline__ float fsig(float x) {
    return 1.0f / (1.0f + __expf(-x));
}
__device__ __forceinline__ float ftanh(float x) {
    float e = __expf(2.0f * x);
    return __fdividef(e - 1.0f, e + 1.0f);
}

// ------------------------------ tile pipeline --------------------------------
// z = A(fp16) @ [Whi + Wlo/2048]^T : main fp32-acc + one fp16-acc correction.
// Tile 128(M)x64(N), 256 thr (4m x 2n warps, 32x32 each), KC=64,
// 3-stage cp.async pipeline (32KB/stage, 96KB/CTA -> 2 CTAs/SM).
// R4/R10-validated skeleton: DO NOT restructure the mainloop.
#define KC 64
#define OFF_AHI 0
#define OFF_BHI 16384
#define OFF_BLO 24576
#define STAGE_BYTES 32768
#define SMEM_TOTAL (3 * STAGE_BYTES)

__device__ __forceinline__ void load_chunk(
    uint32_t sb, int tid,
    const __half* __restrict__ a,
    const __half* __restrict__ bhi, const __half* __restrict__ blo,
    int r0, int n0, int K, int kc)
{
    const int kcol = kc * KC;
    #pragma unroll
    for (int i = 0; i < 4; ++i) {              // A: 128 rows x 8 chunks of 16B
        int q = tid + i * 256;
        int row = q >> 3, jj = q & 7;
        uint32_t so = swz(row * 128 + jj * 16);
        size_t ga = (size_t)(r0 + row) * K + kcol + jj * 8;
        cpa16(sb + OFF_AHI + so, a + ga);
    }
    #pragma unroll
    for (int i = 0; i < 2; ++i) {              // B: 64 rows x 8 chunks of 16B
        int q = tid + i * 256;
        int row = q >> 3, jj = q & 7;
        uint32_t so = swz(row * 128 + jj * 16);
        size_t gb = (size_t)(n0 + row) * K + kcol + jj * 8;
        cpa16(sb + OFF_BHI + so, bhi + gb);
        cpa16(sb + OFF_BLO + so, blo + gb);
    }
    CP_COMMIT();
}

__device__ __forceinline__ void load_b_chunk(
    uint32_t sb, int tid,
    const __half* __restrict__ bhi, const __half* __restrict__ blo,
    int n0, int K, int kc)
{
    const int kcol = kc * KC;
    #pragma unroll
    for (int i = 0; i < 2; ++i) {
        int q = tid + i * 256;
        int row = q >> 3, jj = q & 7;
        uint32_t so = swz(row * 128 + jj * 16);
        size_t gb = (size_t)(n0 + row) * K + kcol + jj * 8;
        cpa16(sb + OFF_BHI + so, bhi + gb);
        cpa16(sb + OFF_BLO + so, blo + gb);
    }
    CP_COMMIT();
}
__device__ __forceinline__ void load_a_chunk(
    uint32_t sb, int tid, const __half* __restrict__ a,
    int r0, int K, int kc)
{
    const int kcol = kc * KC;
    #pragma unroll
    for (int i = 0; i < 4; ++i) {
        int q = tid + i * 256;
        int row = q >> 3, jj = q & 7;
        uint32_t so = swz(row * 128 + jj * 16);
        size_t ga = (size_t)(r0 + row) * K + kcol + jj * 8;
        cpa16(sb + OFF_AHI + so, a + ga);
    }
    CP_COMMIT();
}

// One 128x64 tile: B preload -> dependency spin -> A preload -> mainloop ->
// fused LSTM / pred epilogue. Body identical to R14.
__device__ __forceinline__ void tile_work(
    const __half* __restrict__ a,
    const __half* __restrict__ bhi, const __half* __restrict__ blo,
    int K, const float* __restrict__ bias, int n, int mrow, int t,
    float* __restrict__ outp, __half* __restrict__ hout,
    uint32_t sbase, int tid, volatile int* depcnt, int deptarget)
{
    const int lane = tid & 31, w = tid >> 5;
    const int wm = w & 3, wn = w >> 2;             // 4 (m) x 2 (n) warps
    const int r0 = mrow * 128;
    const int n0 = n * 64;
    const int nch = K / KC;

    float dm[2][4][4];
    uint32_t dc[2][4][2];
    #pragma unroll
    for (int mi = 0; mi < 2; ++mi)
        #pragma unroll
        for (int nj = 0; nj < 4; ++nj) {
            #pragma unroll
            for (int q = 0; q < 4; ++q) dm[mi][nj][q] = 0.0f;
            dc[mi][nj][0] = 0u; dc[mi][nj][1] = 0u;
        }

    // B (constant weights) first; spin on producer row-block; then A.
    load_b_chunk(sbase + 0 * STAGE_BYTES, tid, bhi, blo, n0, K, 0);
    load_b_chunk(sbase + 1 * STAGE_BYTES, tid, bhi, blo, n0, K, 1);
    if (depcnt != nullptr) {
        if (tid == 0) {
            while (*depcnt < deptarget) __nanosleep(128);
            __threadfence();
        }
        __syncthreads();
    }
    load_a_chunk(sbase + 0 * STAGE_BYTES, tid, a, r0, K, 0);
    load_a_chunk(sbase + 1 * STAGE_BYTES, tid, a, r0, K, 1);

    const int lr = lane & 7, sel = lane >> 3;

    for (int kc = 0; kc < nch; ++kc) {
        if (kc + 2 < nch) {
            load_chunk(sbase + ((kc + 2) % 3) * STAGE_BYTES, tid,
                       a, bhi, blo, r0, n0, K, kc + 2);
            CP_WAIT(2);
        } else if (kc + 1 < nch) {
            CP_WAIT(1);
        } else {
            CP_WAIT(0);
        }
        __syncthreads();
        const uint32_t sb = sbase + (kc % 3) * STAGE_BYTES;

        #pragma unroll
        for (int k16 = 0; k16 < 4; ++k16) {
            uint32_t ah[2][4], bh[2][4], bl[2][4];
            #pragma unroll
            for (int mi = 0; mi < 2; ++mi) {
                int row = wm * 32 + mi * 16 + lr + (sel & 1) * 8;
                int kbe = (k16 * 16 + (sel >> 1) * 8) * 2;
                ldsm4(ah[mi], sb + OFF_AHI + swz(row * 128 + kbe));
            }
            #pragma unroll
            for (int njp = 0; njp < 2; ++njp) {
                int nrow = wn * 32 + njp * 16 + lr + (sel >> 1) * 8;
                int kbe = (k16 * 16 + (sel & 1) * 8) * 2;
                uint32_t off = swz(nrow * 128 + kbe);
                ldsm4(bh[njp], sb + OFF_BHI + off);
                ldsm4(bl[njp], sb + OFF_BLO + off);
            }
            #pragma unroll
            for (int mi = 0; mi < 2; ++mi)
                #pragma unroll
                for (int nj = 0; nj < 4; ++nj)
                    mma_f32(dm[mi][nj], ah[mi],
                            bh[nj >> 1][(nj & 1) * 2], bh[nj >> 1][(nj & 1) * 2 + 1]);
            #pragma unroll
            for (int mi = 0; mi < 2; ++mi)
                #pragma unroll
                for (int nj = 0; nj < 4; ++nj)
                    mma_f16(dc[mi][nj], ah[mi],
                            bl[nj >> 1][(nj & 1) * 2], bl[nj >> 1][(nj & 1) * 2 + 1]);
        }
        __syncthreads();
    }

    // ---------------- epilogue ----------------
    const bool isPred = (n0 >= GATES);
    const int qr = lane >> 2, t4 = lane & 3, qc = t4 * 2;
    const bool evenT = ((t4 & 1) == 0);
    const int etid = w * 16 + qr * 2 + (t4 >> 1);            // [0,128)
    const size_t cbase =
        (((size_t)mrow * 64 + (size_t)n) * 128 + (size_t)etid) * 16;

    #pragma unroll
    for (int mi = 0; mi < 2; ++mi) {
        #pragma unroll
        for (int half = 0; half < 2; ++half) {
            const int r = r0 + wm * 32 + mi * 16 + qr + half * 8;
            float4 ca4;
            float* ca = &ca4.x;
            if (!isPred && evenT)
                ca4 = __ldcg(reinterpret_cast<const float4*>(
                    g_cf + cbase + mi * 8 + half * 4));     // L2 (L1 not coherent in-kernel)
            #pragma unroll
            for (int nj = 0; nj < 4; ++nj) {
                const int c = wn * 32 + nj * 8 + qc;
                __half2 hc = *reinterpret_cast<__half2*>(&dc[mi][nj][half]);
                float zx = dm[mi][nj][half * 2 + 0]
                         + INV_LOSCALE * __half2float(__low2half(hc)) + bias[n0 + c];
                float zy = dm[mi][nj][half * 2 + 1]
                         + INV_LOSCALE * __half2float(__high2half(hc)) + bias[n0 + c + 1];
                if (isPred) {
                    float2 v = make_float2(zx, zy);
                    *reinterpret_cast<float2*>(
                        outp + (size_t)r * LDO + (size_t)(t - 1) * OUTU + (n0 - GATES) + c) = v;
                } else {
                    // even t4 holds (zi,zf), odd holds (zg,zo) of the same unit
                    float ox = __shfl_xor_sync(0xffffffffu, zx, 1);
                    float oy = __shfl_xor_sync(0xffffffffu, zy, 1);
                    if (evenT) {
                        const int u = ((n0 + c) >> 2);
                        const size_t off = (size_t)r * UNITS + u;
                        float ig = fsig(zx);
                        float fg = fsig(zy);
                        float gg = ftanh(ox);
                        float og = fsig(oy);
                        float cn = fg * ca[nj] + ig * gg;
                        ca[nj] = cn;
                        hout[off] = __float2half_rn(og * ftanh(cn));
                    }
                }
            }
            if (!isPred && evenT)
                __stcg(reinterpret_cast<float4*>(g_cf + cbase + mi * 8 + half * 4), ca4);
        }
    }
}

// ------------------------------ persistent kernel ----------------------------
__global__ __launch_bounds__(256, 2)
void pbgemm(float* __restrict__ outp)
{
    extern __shared__ __align__(1024) char smem[];
    const uint32_t sbase = smem_u32(smem);
    const int tid = threadIdx.x;
    __shared__ int s_id;

    for (;;) {
        if (tid == 0) s_id = atomicAdd(&g_ticket, 1);
        __syncthreads();
        const int id = s_id;
        if (id >= TTOTAL) break;

        const __half *A, *BH, *BL;
        const float* bias;
        __half* hout;
        int K, n, mrow, t;
        volatile int* dep = nullptr;
        int tgt = 0;

        if (id < T0) {                                   // step 0: gates only
            t = 0; mrow = id >> 6; n = id & 63;
            A = g_a0; BH = g_w0hi; BL = g_w0lo; K = K0;
            bias = g_b0i; hout = g_h1;
        } else if (id < T0 + 95 * TSZ) {                 // steps 1..95
            int q = id - T0;
            t = 1 + q / TSZ;
            int rem = q - (t - 1) * TSZ;
            if (rem < 1024) {                            // gates first (critical)
                mrow = rem >> 6; n = rem & 63;
            } else {                                     // preds trail the step
                int r2 = rem - 1024;
                mrow = r2 >> 2; n = 64 + (r2 & 3);
            }
            A = (t & 1) ? g_h1 : g_h0;                   // hb[t&1]
            hout = ((t + 1) & 1) ? g_h1 : g_h0;          // hb[(t+1)&1]
            BH = g_wthi; BL = g_wtlo; K = UNITS; bias = g_bcd;
            dep = (volatile int*)&g_cnt[(t - 1) * 16 + mrow];
            tgt = 64;                                    // gate tiles only
        } else {                                         // final pred_95 tiles
            int rem = id - (T0 + 95 * TSZ);
            t = STEPS; mrow = rem >> 2; n = 64 + (rem & 3);
            A = g_h0;                                    // h_96 = hb[0]
            hout = g_h1;                                 // unused (pred only)
            BH = g_wthi; BL = g_wtlo; K = UNITS; bias = g_bcd;
            dep = (volatile int*)&g_cnt[95 * 16 + mrow];
            tgt = 64;
        }

        tile_work(A, BH, BL, K, bias, n, mrow, t, outp, hout,
                  sbase, tid, dep, tgt);

        __threadfence();
        __syncthreads();
        if (tid == 0 && t < STEPS && n < 64)             // gate tiles signal
            atomicAdd(&g_cnt[t * 16 + mrow], 1);
    }
}

// ------------------------------ merged prep 1 --------------------------------
__global__ void prep1(const float* __restrict__ b, const float* __restrict__ bd,
                      const float* __restrict__ Wk, const float* __restrict__ Wd) {
    int blk = blockIdx.x;
    if (blk < 17) {
        int j = blk * 256 + threadIdx.x;
        if (j < GATES) {
            float s = b[j];
            #pragma unroll 4
            for (int k = 0; k < 256; ++k)
                s += bd[k] * Wk[(size_t)k * GATES + j];
            g_bcd[icol(j)] = s;
            g_b0i[icol(j)] = b[j];
        } else if (j < NCOMB) {
            g_bcd[j] = bd[j - GATES];
        }
    } else {
        int idx = (blk - 17) * 256 + threadIdx.x;
        if (idx < UNITS * OUTU) {
            int r = idx / OUTU, c = idx % OUTU;
            g_Wcd[(size_t)r * NCOMB + GATES + c] = Wd[idx];
        }
    }
}

// ------------------------------ merged prep splits ---------------------------
#define NB_WS 17408
#define NB_W0 20480
#define NB_A0 10240
#define NB_CI 8192
__global__ void prep_splits(const float* __restrict__ Wk, const float* __restrict__ Wr,
                            const float* __restrict__ x0, const float* __restrict__ h0,
                            const float* __restrict__ c0) {
    int blk = blockIdx.x;
    if (blk < NB_WS) {
        int idx = blk * 256 + threadIdx.x;            // over UNITS*NCOMB
        int k = idx / NCOMB, n = idx - k * NCOMB;
        float v = g_Wcd[idx];
        __half hi = __float2half_rn(v);
        size_t o = (size_t)icol(n) * UNITS + k;
        g_wthi[o] = hi;
        g_wtlo[o] = __float2half_rn((v - __half2float(hi)) * LOSCALE);
    } else if (blk < NB_WS + NB_W0) {
        int idx = (blk - NB_WS) * 256 + threadIdx.x;  // over GATES*K0
        int n = idx & (GATES - 1);
        int k = idx >> 12;
        float v = (k < 256) ? Wk[(size_t)k * GATES + n]
                            : Wr[(size_t)(k - 256) * GATES + n];
        __half hi = __float2half_rn(v);
        size_t o = (size_t)icol(n) * K0 + k;
        g_w0hi[o] = hi;
        g_w0lo[o] = __float2half_rn((v - __half2float(hi)) * LOSCALE);
    } else if (blk < NB_WS + NB_W0 + NB_A0) {
        int idx = (blk - NB_WS - NB_W0) * 256 + threadIdx.x;  // over BATCH*K0
        int r = idx / K0, k = idx - r * K0;
        float v = (k < 256) ? x0[(size_t)r * 256 + k] : h0[(size_t)r * UNITS + (k - 256)];
        g_a0[idx] = __float2half_rn(v);
    } else {
        int L = (blk - NB_WS - NB_W0 - NB_A0) * 256 + threadIdx.x;  // over BATCH*UNITS
        int mt = L >> 17;            // 64 nt * 2048 per m-tile
        int rem = L & 131071;
        int nt = rem >> 11;          // 2048 per n-tile
        int rem2 = rem & 2047;
        int etid = rem2 >> 4, pos = rem2 & 15;
        int ww = etid >> 4, q = etid & 15;
        int qr = q >> 1, th = q & 1;
        int wm = ww & 3, wn = ww >> 2;
        int mi = pos >> 3, half = (pos >> 2) & 1, nj = pos & 3;
        int r = mt * 128 + wm * 32 + mi * 16 + qr + half * 8;
        int u = nt * 16 + wn * 8 + nj * 2 + th;
        g_cf[L] = c0[(size_t)r * UNITS + u];
    }
}

// ------------------------------ fp32 prep GEMM -------------------------------
__global__ __launch_bounds__(256)
void sgemm128(const float* __restrict__ A, int lda,
              const float* __restrict__ B, int ldb, int K,
              const float* __restrict__ Cadd,
              float* __restrict__ C, int ldc) {
    __shared__ float As[8][128];
    __shared__ float Bs[8][128];
    const int tid = threadIdx.x;
    const int tx = tid & 15, ty = tid >> 4;
    const int row0 = blockIdx.y * 128, col0 = blockIdx.x * 128;
    float acc[8][8];
    #pragma unroll
    for (int i = 0; i < 8; ++i)
        #pragma unroll
        for (int j = 0; j < 8; ++j) acc[i][j] = 0.0f;
    const int arow = tid >> 1, acol = (tid & 1) << 2;
    const int brow = tid >> 5, bcol = (tid & 31) << 2;
    const float* Arow = A + (size_t)(row0 + arow) * lda + acol;
    const float* Brow = B + (size_t)brow * ldb + col0 + bcol;
    for (int k0 = 0; k0 < K; k0 += 8) {
        float4 av = *reinterpret_cast<const float4*>(Arow + k0);
        float4 bv = *reinterpret_cast<const float4*>(Brow + (size_t)k0 * ldb);
        As[acol + 0][arow] = av.x; As[acol + 1][arow] = av.y;
        As[acol + 2][arow] = av.z; As[acol + 3][arow] = av.w;
        *reinterpret_cast<float4*>(&Bs[brow][bcol]) = bv;
        __syncthreads();
        #pragma unroll
        for (int k = 0; k < 8; ++k) {
            float a[8], bb[8];
            #pragma unroll
            for (int i = 0; i < 8; ++i) a[i] = As[k][ty * 8 + i];
            #pragma unroll
            for (int j = 0; j < 8; ++j) bb[j] = Bs[k][tx * 8 + j];
            #pragma unroll
            for (int i = 0; i < 8; ++i)
                #pragma unroll
                for (int j = 0; j < 8; ++j)
                    acc[i][j] = fmaf(a[i], bb[j], acc[i][j]);
        }
        __syncthreads();
    }
    const int gcol = col0 + tx * 8;
    #pragma unroll
    for (int i = 0; i < 8; ++i) {
        int r = row0 + ty * 8 + i;
        #pragma unroll
        for (int j = 0; j < 8; j += 4) {
            float4 v = make_float4(acc[i][j], acc[i][j+1], acc[i][j+2], acc[i][j+3]);
            if (Cadd) {
                float4 a4 = *reinterpret_cast<const float4*>(Cadd + (size_t)r * ldb + gcol + j);
                v.x += a4.x; v.y += a4.y; v.z += a4.z; v.w += a4.w;
            }
            *reinterpret_cast<float4*>(C + (size_t)r * ldc + gcol + j) = v;
        }
    }
}

// ------------------------------ launch ---------------------------------------
extern "C" void kernel_launch(void* const* d_in, const int* in_sizes, int n_in,
                              void* d_out, int out_size) {
    const float* x0 = (const float*)d_in[0];
    const float* h0 = (const float*)d_in[1];
    const float* c0 = (const float*)d_in[2];
    const float* Wk = (const float*)d_in[3];
    const float* Wr = (const float*)d_in[4];
    const float* b  = (const float*)d_in[5];
    const float* Wd = (const float*)d_in[6];
    const float* bd = (const float*)d_in[7];
    float* out = (float*)d_out;

    cudaFuncSetAttribute(pbgemm, cudaFuncAttributeMaxDynamicSharedMemorySize, SMEM_TOTAL);

    float* pWcd;
    int *pTicket, *pCnt;
    cudaGetSymbolAddress((void**)&pWcd, g_Wcd);
    cudaGetSymbolAddress((void**)&pTicket, g_ticket);
    cudaGetSymbolAddress((void**)&pCnt, g_cnt);

    // reset persistent-schedule state (graph-replay-safe, deterministic)
    cudaMemsetAsync(pTicket, 0, sizeof(int), 0);
    cudaMemsetAsync(pCnt, 0, STEPS * 16 * sizeof(int), 0);

    // prep
    prep1<<<17 + 1024, 256>>>(b, bd, Wk, Wd);
    sgemm128<<<dim3(GATES / 128, UNITS / 128), 256>>>(
        Wd, OUTU, Wk, GATES, 256, Wr, pWcd, NCOMB);      // Wc = Wd@Wk + Wr
    prep_splits<<<NB_WS + NB_W0 + NB_A0 + NB_CI, 256>>>(Wk, Wr, x0, h0, c0);

    // all 97 steps in ONE persistent launch (ticket + per-(step,mrow) deps)
    pbgemm<<<NCTAS, 256, SMEM_TOTAL>>>(out);
}